// round 14
// baseline (speedup 1.0000x reference)
#include <cuda_runtime.h>
#include <cuda_bf16.h>
#include <math.h>
#include <stdint.h>

// ---------------------------------------------------------------------------
// Problem constants
// ---------------------------------------------------------------------------
#define CC      256
#define WS      8
#define NTOK    64
#define NF      66
#define HEADS   8
#define HD      32
#define NWIN    2048
#define TOKS    131072
#define SCALE   0.17677669529663687f

// ---------------------------------------------------------------------------
// Scratch
// ---------------------------------------------------------------------------
__device__ __nv_bfloat16 g_xlnbf[ (size_t)TOKS * CC ];
__device__ __nv_bfloat16 g_qkvs[ (size_t)NWIN * NTOK * 3 * CC ];
__device__ __nv_bfloat16 g_qkvf[ (size_t)NWIN * NF * 3 * CC ];
__device__ __nv_bfloat16 g_attnh[ (size_t)NWIN * NTOK * CC ];   // spatial attn out (bf16)
__device__ __nv_bfloat16 g_attnbf[ (size_t)NWIN * NTOK * CC ];  // attn + xr (bf16)
__device__ float g_outf[ (size_t)NWIN * NF   * CC ];
__device__ float g_x2  [ (size_t)TOKS * CC ];
__device__ __nv_bfloat16 g_hln[ (size_t)TOKS * CC ];
__device__ __nv_bfloat16 g_h1 [ (size_t)TOKS * 4 * CC ];
__device__ __nv_bfloat16 g_w1bf[ 1024 * 256 ];
__device__ __nv_bfloat16 g_w2bf[ 256 * 1024 ];
__device__ __nv_bfloat16 g_wqbf[ 768 * 256 ];
__device__ __nv_bfloat16 g_wpbf[ 256 * 256 ];
__device__ float g_Fc[ 33 * 34 ];
__device__ float g_Fs[ 33 * 34 ];
__device__ float g_Ic[ 33 * 34 ];
__device__ float g_Is[ 33 * 34 ];

// ---------------------------------------------------------------------------
// Helpers
// ---------------------------------------------------------------------------
__device__ __forceinline__ uint32_t smem_u32(const void* p) {
    uint32_t a;
    asm("{ .reg .u64 t; cvta.to.shared.u64 t, %1; cvt.u32.u64 %0, t; }"
        : "=r"(a) : "l"(p));
    return a;
}

#define CP_ASYNC16(dst_u32, src_ptr) \
    asm volatile("cp.async.cg.shared.global [%0], [%1], 16;" \
        :: "r"(dst_u32), "l"(src_ptr))
#define CP_COMMIT() asm volatile("cp.async.commit_group;")
#define CP_WAIT1()  asm volatile("cp.async.wait_group 1;")
#define CP_WAIT0()  asm volatile("cp.async.wait_group 0;")

__device__ __forceinline__ void mma16n8k16bf(float* c, const uint32_t* a,
                                             const uint32_t* b) {
    asm volatile(
        "mma.sync.aligned.m16n8k16.row.col.f32.bf16.bf16.f32 "
        "{%0,%1,%2,%3}, {%4,%5,%6,%7}, {%8,%9}, {%0,%1,%2,%3};"
        : "+f"(c[0]), "+f"(c[1]), "+f"(c[2]), "+f"(c[3])
        : "r"(a[0]), "r"(a[1]), "r"(a[2]), "r"(a[3]), "r"(b[0]), "r"(b[1]));
}

__device__ __forceinline__ int win2pix(int t) {
    int b   = t >> 16;
    int rem = t & 65535;
    int wl  = rem >> 6;
    int n   = rem & 63;
    int wh  = wl >> 5, ww = wl & 31;
    int i   = n >> 3,  j  = n & 7;
    return (b * 256 + wh * 8 + i) * 256 + (ww * 8 + j);
}

__device__ __forceinline__ float dot4(float4 a, float4 b) {
    return a.x * b.x + a.y * b.y + a.z * b.z + a.w * b.w;
}

__device__ __forceinline__ void bf8_to_f8(uint4 r, float* o) {
    const __nv_bfloat162* p = (const __nv_bfloat162*)&r;
    #pragma unroll
    for (int i = 0; i < 4; i++) {
        float2 f = __bfloat1622float2(p[i]);
        o[2 * i] = f.x; o[2 * i + 1] = f.y;
    }
}

// ---------------------------------------------------------------------------
// DFT matrix init
// ---------------------------------------------------------------------------
__global__ void init_dft_kernel() {
    int i = blockIdx.x * blockDim.x + threadIdx.x;
    if (i < 33 * 34) {
        int r = i / 34, c = i % 34;
        float fc = 0.f, fs = 0.f, ic = 0.f, is = 0.f;
        if (c < 33) {
            float cs = cospif((float)(r * c) / 32.0f);
            float sn = sinpif((float)(r * c) / 32.0f);
            fc = 0.125f * cs;
            fs = -0.125f * sn;
            if (c == 0)       ic = 0.125f;
            else if (c == 32) ic = 0.125f * cospif((float)r);
            else              ic = 0.25f * cs;
            is = -0.25f * sn;
        }
        g_Fc[i] = fc; g_Fs[i] = fs; g_Ic[i] = ic; g_Is[i] = is;
    }
}

__global__ void conv_w_kernel(const float* __restrict__ w1,
                              const float* __restrict__ w2,
                              const float* __restrict__ wq,
                              const float* __restrict__ wp) {
    int i = blockIdx.x * blockDim.x + threadIdx.x;
    if (i < 1024 * 256) {
        g_w1bf[i] = __float2bfloat16_rn(w1[i]);
        g_w2bf[i] = __float2bfloat16_rn(w2[i]);
    }
    if (i < 768 * 256)  g_wqbf[i] = __float2bfloat16_rn(wq[i]);
    if (i < 256 * 256)  g_wpbf[i] = __float2bfloat16_rn(wp[i]);
}

// ---------------------------------------------------------------------------
// LayerNorm -> bf16, warp-per-row
// ---------------------------------------------------------------------------
__global__ __launch_bounds__(256)
void ln_bf16_kernel(const float* __restrict__ xin,
                    const float* __restrict__ w,
                    const float* __restrict__ b,
                    __nv_bfloat16* __restrict__ out, int winmap) {
    int warp = threadIdx.x >> 5, lane = threadIdx.x & 31;
    int t = blockIdx.x * 8 + warp;
    int rin = winmap ? win2pix(t) : t;
    const float4* src = (const float4*)(xin + (size_t)rin * CC) + lane * 2;
    float4 v0 = src[0], v1 = src[1];
    float s = v0.x + v0.y + v0.z + v0.w + v1.x + v1.y + v1.z + v1.w;
    float sq = v0.x * v0.x + v0.y * v0.y + v0.z * v0.z + v0.w * v0.w
             + v1.x * v1.x + v1.y * v1.y + v1.z * v1.z + v1.w * v1.w;
    #pragma unroll
    for (int o = 16; o; o >>= 1) {
        s  += __shfl_xor_sync(0xffffffffu, s,  o);
        sq += __shfl_xor_sync(0xffffffffu, sq, o);
    }
    float mean = s * (1.0f / CC);
    float var  = sq * (1.0f / CC) - mean * mean;
    float rstd = rsqrtf(var + 1e-5f);
    const float4* wp4 = (const float4*)w + lane * 2;
    const float4* bp4 = (const float4*)b + lane * 2;
    float4 w0 = wp4[0], w1 = wp4[1];
    float4 b0 = bp4[0], b1 = bp4[1];
    __nv_bfloat162 o4[4];
    o4[0] = __floats2bfloat162_rn((v0.x - mean) * rstd * w0.x + b0.x,
                                  (v0.y - mean) * rstd * w0.y + b0.y);
    o4[1] = __floats2bfloat162_rn((v0.z - mean) * rstd * w0.z + b0.z,
                                  (v0.w - mean) * rstd * w0.w + b0.w);
    o4[2] = __floats2bfloat162_rn((v1.x - mean) * rstd * w1.x + b1.x,
                                  (v1.y - mean) * rstd * w1.y + b1.y);
    o4[3] = __floats2bfloat162_rn((v1.z - mean) * rstd * w1.z + b1.z,
                                  (v1.w - mean) * rstd * w1.w + b1.w);
    *(uint4*)(out + (size_t)t * CC + lane * 8) = *(uint4*)o4;
}

// ---------------------------------------------------------------------------
// bf16 mma.sync GEMM, 512 threads / 16 warps, 128x256 tile, warp 64x32.
// EPI: 1 GELU->bf16; 2 +res fp32; 3 winrev+res fp32; 4 plain bf16;
//      5 plain bf16 + fused spectral DFT (qkv): M-tile = 2 windows.
// ---------------------------------------------------------------------------
#define HPAD 72
#define A_STG_H (128 * HPAD)
#define B_STG_H (256 * HPAD)
#define BF_SMEM (3 * (A_STG_H + B_STG_H) * 2)
#define TPAD 264            // DFT staging tile row stride (bf16)

template<int EPI>
__global__ __launch_bounds__(512, 1)
void gemm_bf16(const __nv_bfloat16* __restrict__ A,
               const __nv_bfloat16* __restrict__ W,
               const float* __restrict__ bias, void* __restrict__ Cv,
               int M, int N, int K, const float* __restrict__ res,
               __nv_bfloat16* __restrict__ qkvf_out) {
    extern __shared__ char smc[];
    __nv_bfloat16* AsBase = (__nv_bfloat16*)smc;
    __nv_bfloat16* BsBase = AsBase + 3 * A_STG_H;
    uint32_t sA = smem_u32(AsBase);
    uint32_t sB = smem_u32(BsBase);

    int tid = threadIdx.x;
    int m0 = blockIdx.y * 128, n0 = blockIdx.x * 256;
    int wid = tid >> 5, lane = tid & 31;
    int wm = (wid & 1) * 64, wn = (wid >> 1) * 32;
    int grp = lane >> 2, tg = lane & 3;

    float acc[4][4][4];
    #pragma unroll
    for (int a = 0; a < 4; a++)
        #pragma unroll
        for (int b = 0; b < 4; b++)
            #pragma unroll
            for (int c = 0; c < 4; c++) acc[a][b][c] = 0.f;

    const int NC = K / 64;

    #pragma unroll
    for (int pc = 0; pc < 2; pc++) {
        #pragma unroll
        for (int t = 0; t < 2; t++) {
            int idx = tid + t * 512;
            int row = idx >> 3, q = idx & 7;
            CP_ASYNC16(sA + (uint32_t)(pc * A_STG_H + row * HPAD + q * 8) * 2u,
                       A + (size_t)(m0 + row) * K + pc * 64 + q * 8);
        }
        #pragma unroll
        for (int t = 0; t < 4; t++) {
            int idx = tid + t * 512;
            int row = idx >> 3, q = idx & 7;
            CP_ASYNC16(sB + (uint32_t)(pc * B_STG_H + row * HPAD + q * 8) * 2u,
                       W + (size_t)(n0 + row) * K + pc * 64 + q * 8);
        }
        CP_COMMIT();
    }

    for (int i = 0; i < NC; i++) {
        if (i + 1 < NC) CP_WAIT1(); else CP_WAIT0();
        __syncthreads();
        if (i + 2 < NC) {
            int st = (i + 2) % 3;
            #pragma unroll
            for (int t = 0; t < 2; t++) {
                int idx = tid + t * 512;
                int row = idx >> 3, q = idx & 7;
                CP_ASYNC16(sA + (uint32_t)(st * A_STG_H + row * HPAD + q * 8) * 2u,
                           A + (size_t)(m0 + row) * K + (i + 2) * 64 + q * 8);
            }
            #pragma unroll
            for (int t = 0; t < 4; t++) {
                int idx = tid + t * 512;
                int row = idx >> 3, q = idx & 7;
                CP_ASYNC16(sB + (uint32_t)(st * B_STG_H + row * HPAD + q * 8) * 2u,
                           W + (size_t)(n0 + row) * K + (i + 2) * 64 + q * 8);
            }
            CP_COMMIT();
        }

        const __nv_bfloat16* As = AsBase + (i % 3) * A_STG_H;
        const __nv_bfloat16* Bs = BsBase + (i % 3) * B_STG_H;
        #pragma unroll
        for (int ks = 0; ks < 4; ks++) {
            uint32_t af[4][4];
            uint32_t bf[4][2];
            #pragma unroll
            for (int mi = 0; mi < 4; mi++) {
                int r = wm + mi * 16 + grp;
                af[mi][0] = *(const uint32_t*)(As + r * HPAD + ks * 16 + tg * 2);
                af[mi][1] = *(const uint32_t*)(As + (r + 8) * HPAD + ks * 16 + tg * 2);
                af[mi][2] = *(const uint32_t*)(As + r * HPAD + ks * 16 + tg * 2 + 8);
                af[mi][3] = *(const uint32_t*)(As + (r + 8) * HPAD + ks * 16 + tg * 2 + 8);
            }
            #pragma unroll
            for (int ni = 0; ni < 4; ni++) {
                int r = wn + ni * 8 + grp;
                bf[ni][0] = *(const uint32_t*)(Bs + r * HPAD + ks * 16 + tg * 2);
                bf[ni][1] = *(const uint32_t*)(Bs + r * HPAD + ks * 16 + tg * 2 + 8);
            }
            #pragma unroll
            for (int mi = 0; mi < 4; mi++)
                #pragma unroll
                for (int ni = 0; ni < 4; ni++)
                    mma16n8k16bf(acc[mi][ni], af[mi], bf[ni]);
        }
    }

    if (EPI == 5) __syncthreads();   // pipeline smem about to be reused

    __nv_bfloat16* tile = (__nv_bfloat16*)smc;   // [128][TPAD] staging (EPI 5)

    #pragma unroll
    for (int mi = 0; mi < 4; mi++) {
        #pragma unroll
        for (int half = 0; half < 2; half++) {
            int m = m0 + wm + mi * 16 + grp + half * 8;
            size_t orow = (EPI == 3) ? (size_t)win2pix(m) * N : (size_t)m * N;
            #pragma unroll
            for (int ni = 0; ni < 4; ni++) {
                int n = n0 + wn + ni * 8 + tg * 2;
                float vx = acc[mi][ni][half * 2 + 0] + bias[n];
                float vy = acc[mi][ni][half * 2 + 1] + bias[n + 1];
                if (EPI == 1) {
                    vx = 0.5f * vx * (1.0f + erff(vx * 0.7071067811865476f));
                    vy = 0.5f * vy * (1.0f + erff(vy * 0.7071067811865476f));
                    ((__nv_bfloat162*)Cv)[(orow + n) >> 1] = __floats2bfloat162_rn(vx, vy);
                } else if (EPI == 4 || EPI == 5) {
                    __nv_bfloat162 pk = __floats2bfloat162_rn(vx, vy);
                    ((__nv_bfloat162*)Cv)[(orow + n) >> 1] = pk;
                    if (EPI == 5) {
                        int r = m - m0, c = n - n0;
                        *(__nv_bfloat162*)(tile + r * TPAD + c) = pk;
                    }
                } else {
                    vx += res[orow + n];
                    vy += res[orow + n + 1];
                    *(float2*)((float*)Cv + orow + n) = make_float2(vx, vy);
                }
            }
        }
    }

    if (EPI == 5) {
        float* Fcs = (float*)(smc + 128 * TPAD * 2);
        float* Fss = Fcs + 33 * 34;
        for (int m = tid; m < 33 * 34; m += 512) { Fcs[m] = g_Fc[m]; Fss[m] = g_Fs[m]; }
        __syncthreads();

        int sub = tid >> 8;           // which of the 2 windows in this M-tile
        int ch  = tid & 255;          // channel within this N-tile
        int w   = blockIdx.y * 2 + sub;
        const __nv_bfloat16* col = tile + (sub * 64) * TPAD + ch;

        float e[33], o[32];
        e[0]  = __bfloat162float(col[0]);
        e[32] = __bfloat162float(col[32 * TPAD]);
        #pragma unroll
        for (int n = 1; n < 32; n++) {
            float a = __bfloat162float(col[n * TPAD]);
            float b = __bfloat162float(col[(64 - n) * TPAD]);
            e[n] = a + b;
            o[n] = a - b;
        }

        float bb = bias[n0 + ch];
        __nv_bfloat16* dst = qkvf_out + (size_t)w * NF * 768 + (n0 + ch);

        #pragma unroll 1
        for (int f = 0; f < 32; f += 2) {
            const float* R0 = Fcs + f * 34;
            const float* R1 = R0 + 34;
            float s0 = 0.f, s0b = 0.f, s1 = 0.f, s1b = 0.f;
            #pragma unroll
            for (int n = 0; n < 32; n += 2) {
                s0  += R0[n] * e[n];     s0b += R0[n + 1] * e[n + 1];
                s1  += R1[n] * e[n];     s1b += R1[n + 1] * e[n + 1];
            }
            s0 += R0[32] * e[32];
            s1 += R1[32] * e[32];
            dst[(size_t)f * 768]       = __float2bfloat16_rn(s0 + s0b + ((f == 0) ? -7.0f * bb : bb));
            dst[(size_t)(f + 1) * 768] = __float2bfloat16_rn(s1 + s1b + bb);
        }
        {
            const float* R0 = Fcs + 32 * 34;
            float s0 = 0.f, s0b = 0.f;
            #pragma unroll
            for (int n = 0; n < 32; n += 2) {
                s0 += R0[n] * e[n]; s0b += R0[n + 1] * e[n + 1];
            }
            s0 += R0[32] * e[32];
            dst[(size_t)32 * 768] = __float2bfloat16_rn(s0 + s0b + bb);
        }

        dst[(size_t)33 * 768] = __float2bfloat16_rn(bb);
        dst[(size_t)65 * 768] = __float2bfloat16_rn(bb);

        #pragma unroll 1
        for (int f = 1; f < 31; f += 2) {
            const float* R0 = Fss + f * 34;
            const float* R1 = R0 + 34;
            float s0 = 0.f, s0b = 0.f, s1 = 0.f, s1b = 0.f;
            #pragma unroll
            for (int n = 1; n < 31; n += 2) {
                s0  += R0[n] * o[n];     s0b += R0[n + 1] * o[n + 1];
                s1  += R1[n] * o[n];     s1b += R1[n + 1] * o[n + 1];
            }
            s0 += R0[31] * o[31];
            s1 += R1[31] * o[31];
            dst[(size_t)(33 + f) * 768] = __float2bfloat16_rn(s0 + s0b + bb);
            dst[(size_t)(34 + f) * 768] = __float2bfloat16_rn(s1 + s1b + bb);
        }
        {
            const float* R0 = Fss + 31 * 34;
            float s0 = 0.f, s0b = 0.f;
            #pragma unroll
            for (int n = 1; n < 31; n += 2) {
                s0 += R0[n] * o[n]; s0b += R0[n + 1] * o[n + 1];
            }
            s0 += R0[31] * o[31];
            dst[(size_t)64 * 768] = __float2bfloat16_rn(s0 + s0b + bb);
        }
    }
}

// ---------------------------------------------------------------------------
// Inverse rfft: attnbf = bf16(attn(bf16) + irfft(outf))
// ---------------------------------------------------------------------------
__global__ __launch_bounds__(256)
void ifft_acc_kernel(const float* __restrict__ outf,
                     const __nv_bfloat16* __restrict__ attn,
                     __nv_bfloat16* __restrict__ attnbf) {
    __shared__ float Ic[33 * 34];
    __shared__ float Is[33 * 34];
    int w = blockIdx.x;
    int c = threadIdx.x;
    for (int m = c; m < 33 * 34; m += 256) { Ic[m] = g_Ic[m]; Is[m] = g_Is[m]; }

    float fr[NF];
    const float* src = outf + (size_t)w * NF * CC + c;
    #pragma unroll 11
    for (int r = 0; r < NF; r++) fr[r] = src[(size_t)r * CC];
    __syncthreads();

    const __nv_bfloat16* ain = attn + (size_t)w * NTOK * CC + c;
    __nv_bfloat16* dst = attnbf + (size_t)w * NTOK * CC + c;
    #pragma unroll 1
    for (int n = 0; n < 32; n += 2) {
        const float* C0 = Ic + n * 34;
        const float* C1 = C0 + 34;
        const float* S0 = Is + n * 34;
        const float* S1 = S0 + 34;
        float a0 = 0.f, a0b = 0.f, a1 = 0.f, a1b = 0.f;
        #pragma unroll
        for (int r = 0; r < 32; r += 2) {
            a0  += C0[r] * fr[r];     a0b += C0[r + 1] * fr[r + 1];
            a1  += C1[r] * fr[r];     a1b += C1[r + 1] * fr[r + 1];
        }
        a0 += C0[32] * fr[32];
        a1 += C1[32] * fr[32];
        float b0 = 0.f, b0b = 0.f, b1 = 0.f, b1b = 0.f;
        #pragma unroll
        for (int r = 1; r < 31; r += 2) {
            b0  += S0[r] * fr[33 + r];     b0b += S0[r + 1] * fr[34 + r];
            b1  += S1[r] * fr[33 + r];     b1b += S1[r + 1] * fr[34 + r];
        }
        b0 += S0[31] * fr[64];
        b1 += S1[31] * fr[64];
        float A0 = a0 + a0b, B0 = b0 + b0b;
        float A1 = a1 + a1b, B1 = b1 + b1b;
        dst[(size_t)n * CC] =
            __float2bfloat16_rn(__bfloat162float(ain[(size_t)n * CC]) + A0 + B0);
        if (n >= 1)
            dst[(size_t)(64 - n) * CC] =
                __float2bfloat16_rn(__bfloat162float(ain[(size_t)(64 - n) * CC]) + A0 - B0);
        dst[(size_t)(n + 1) * CC] =
            __float2bfloat16_rn(__bfloat162float(ain[(size_t)(n + 1) * CC]) + A1 + B1);
        dst[(size_t)(63 - n) * CC] =
            __float2bfloat16_rn(__bfloat162float(ain[(size_t)(63 - n) * CC]) + A1 - B1);
    }
    {
        const float* C0 = Ic + 32 * 34;
        float a0 = 0.f, a0b = 0.f;
        #pragma unroll
        for (int r = 0; r < 32; r += 2) {
            a0 += C0[r] * fr[r]; a0b += C0[r + 1] * fr[r + 1];
        }
        a0 += C0[32] * fr[32];
        dst[(size_t)32 * CC] =
            __float2bfloat16_rn(__bfloat162float(ain[(size_t)32 * CC]) + a0 + a0b);
    }
}

// ---------------------------------------------------------------------------
// Spatial window attention, bf16 qkv input, bf16 out
// ---------------------------------------------------------------------------
__global__ void attn_kernel(const __nv_bfloat16* __restrict__ qkv,
                            const float* __restrict__ rpb,
                            __nv_bfloat16* __restrict__ outp) {
    const int NT = NTOK;
    __shared__ float ks[NT][36];
    __shared__ float vs[NT][36];
    __shared__ float ss[NT][65];
    __shared__ float rpb_s[225];

    int w = blockIdx.x, h = blockIdx.y;
    int row = threadIdx.x;

    float4 qv[8];
    {
        const uint4* base = (const uint4*)(qkv + ((size_t)w * NT + row) * 768 + h * 32);
        #pragma unroll
        for (int i = 0; i < 4; i++) {
            float qf[8];
            bf8_to_f8(base[i], qf);
            qv[2 * i]     = make_float4(qf[0] * SCALE, qf[1] * SCALE, qf[2] * SCALE, qf[3] * SCALE);
            qv[2 * i + 1] = make_float4(qf[4] * SCALE, qf[5] * SCALE, qf[6] * SCALE, qf[7] * SCALE);
            bf8_to_f8(base[32 + i], &ks[row][i * 8]);
            bf8_to_f8(base[64 + i], &vs[row][i * 8]);
        }
    }
    for (int m = row; m < 225; m += NT) rpb_s[m] = rpb[m * HEADS + h];
    __syncthreads();

    int yi = row >> 3, xi = row & 7;
    float mx = -1e30f;
    for (int j = 0; j < NT; j += 4) {
        const float4* k0 = (const float4*)ks[j + 0];
        const float4* k1 = (const float4*)ks[j + 1];
        const float4* k2 = (const float4*)ks[j + 2];
        const float4* k3 = (const float4*)ks[j + 3];
        float s0 = 0.f, s1 = 0.f, s2 = 0.f, s3 = 0.f;
        #pragma unroll
        for (int d4 = 0; d4 < 8; d4++) {
            float4 q = qv[d4];
            s0 += dot4(q, k0[d4]);
            s1 += dot4(q, k1[d4]);
            s2 += dot4(q, k2[d4]);
            s3 += dot4(q, k3[d4]);
        }
        int bi = (yi + 7) * 15 + (xi + 7);
        s0 += rpb_s[bi - ((j + 0) >> 3) * 15 - ((j + 0) & 7)];
        s1 += rpb_s[bi - ((j + 1) >> 3) * 15 - ((j + 1) & 7)];
        s2 += rpb_s[bi - ((j + 2) >> 3) * 15 - ((j + 2) & 7)];
        s3 += rpb_s[bi - ((j + 3) >> 3) * 15 - ((j + 3) & 7)];
        ss[row][j + 0] = s0; ss[row][j + 1] = s1;
        ss[row][j + 2] = s2; ss[row][j + 3] = s3;
        mx = fmaxf(mx, fmaxf(fmaxf(s0, s1), fmaxf(s2, s3)));
    }

    float sum0 = 0.f, sum1 = 0.f;
    for (int jj = 0; jj < NT; jj += 2) {
        float e0 = __expf(ss[row][jj] - mx);
        float e1 = __expf(ss[row][jj + 1] - mx);
        ss[row][jj] = e0; ss[row][jj + 1] = e1;
        sum0 += e0; sum1 += e1;
    }
    float inv = 1.0f / (sum0 + sum1);

    float4 av[8];
    #pragma unroll
    for (int d4 = 0; d4 < 8; d4++) av[d4] = make_float4(0.f, 0.f, 0.f, 0.f);
    for (int jj = 0; jj < NT; jj += 2) {
        float p0 = ss[row][jj];
        float p1 = ss[row][jj + 1];
        const float4* v0 = (const float4*)vs[jj];
        const float4* v1 = (const float4*)vs[jj + 1];
        #pragma unroll
        for (int d4 = 0; d4 < 8; d4++) {
            float4 a = av[d4];
            float4 x0 = v0[d4], x1 = v1[d4];
            a.x += p0 * x0.x + p1 * x1.x;
            a.y += p0 * x0.y + p1 * x1.y;
            a.z += p0 * x0.z + p1 * x1.z;
            a.w += p0 * x0.w + p1 * x1.w;
            av[d4] = a;
        }
    }

    __nv_bfloat162* ob = (__nv_bfloat162*)(outp + ((size_t)w * NT + row) * CC + h * 32);
    #pragma unroll
    for (int d4 = 0; d4 < 8; d4++) {
        float4 a = av[d4];
        ob[2 * d4]     = __floats2bfloat162_rn(a.x * inv, a.y * inv);
        ob[2 * d4 + 1] = __floats2bfloat162_rn(a.z * inv, a.w * inv);
    }
}

// ---------------------------------------------------------------------------
// Spectral attention: 2 windows per block, bf16 input
// ---------------------------------------------------------------------------
__global__ __launch_bounds__(160)
void attn_spec2_kernel(const __nv_bfloat16* __restrict__ qkv,
                       float* __restrict__ outp) {
    __shared__ float ks[2][NF][36];
    __shared__ float vs[2][NF][36];
    __shared__ float ss[2][NF][67];

    int w2 = blockIdx.x, h = blockIdx.y;
    int tid = threadIdx.x;
    int sub = tid / NF;
    int row = tid % NF;
    bool act = tid < 2 * NF;
    int w = w2 * 2 + sub;

    float4 qv[8];
    if (act) {
        const uint4* base = (const uint4*)(qkv + ((size_t)w * NF + row) * 768 + h * 32);
        #pragma unroll
        for (int i = 0; i < 4; i++) {
            float qf[8];
            bf8_to_f8(base[i], qf);
            qv[2 * i]     = make_float4(qf[0] * SCALE, qf[1] * SCALE, qf[2] * SCALE, qf[3] * SCALE);
            qv[2 * i + 1] = make_float4(qf[4] * SCALE, qf[5] * SCALE, qf[6] * SCALE, qf[7] * SCALE);
            bf8_to_f8(base[32 + i], &ks[sub][row][i * 8]);
            bf8_to_f8(base[64 + i], &vs[sub][row][i * 8]);
        }
    }
    __syncthreads();
    if (!act) return;

    float mx = -1e30f;
    int j = 0;
    for (; j + 3 < NF; j += 4) {
        const float4* k0 = (const float4*)ks[sub][j + 0];
        const float4* k1 = (const float4*)ks[sub][j + 1];
        const float4* k2 = (const float4*)ks[sub][j + 2];
        const float4* k3 = (const float4*)ks[sub][j + 3];
        float s0 = 0.f, s1 = 0.f, s2 = 0.f, s3 = 0.f;
        #pragma unroll
        for (int d4 = 0; d4 < 8; d4++) {
            float4 q = qv[d4];
            s0 += dot4(q, k0[d4]);
            s1 += dot4(q, k1[d4]);
            s2 += dot4(q, k2[d4]);
            s3 += dot4(q, k3[d4]);
        }
        ss[sub][row][j + 0] = s0; ss[sub][row][j + 1] = s1;
        ss[sub][row][j + 2] = s2; ss[sub][row][j + 3] = s3;
        mx = fmaxf(mx, fmaxf(fmaxf(s0, s1), fmaxf(s2, s3)));
    }
    for (; j < NF; j++) {
        const float4* k0 = (const float4*)ks[sub][j];
        float s0 = 0.f;
        #pragma unroll
        for (int d4 = 0; d4 < 8; d4++) s0 += dot4(qv[d4], k0[d4]);
        ss[sub][row][j] = s0;
        mx = fmaxf(mx, s0);
    }

    float sum0 = 0.f, sum1 = 0.f;
    for (int jj = 0; jj + 1 < NF; jj += 2) {
        float e0 = __expf(ss[sub][row][jj] - mx);
        float e1 = __expf(ss[sub][row][jj + 1] - mx);
        ss[sub][row][jj] = e0; ss[sub][row][jj + 1] = e1;
        sum0 += e0; sum1 += e1;
    }
    float inv = 1.0f / (sum0 + sum1);

    float4 av[8];
    #pragma unroll
    for (int d4 = 0; d4 < 8; d4++) av[d4] = make_float4(0.f, 0.f, 0.f, 0.f);
    for (int jj = 0; jj + 1 < NF; jj += 2) {
        float p0 = ss[sub][row][jj];
        float p1 = ss[sub][row][jj + 1];
        const float4* v0 = (const float4*)vs[sub][jj];
        const float4* v1 = (const float4*)vs[sub][jj + 1];
        #pragma unroll
        for (int d4 = 0; d4 < 8; d4++) {
            float4 a = av[d4];
            float4 x0 = v0[d4], x1 = v1[d4];
            a.x += p0 * x0.x + p1 * x1.x;
            a.y += p0 * x0.y + p1 * x1.y;
            a.z += p0 * x0.z + p1 * x1.z;
            a.w += p0 * x0.w + p1 * x1.w;
            av[d4] = a;
        }
    }

    float4* ob = (float4*)(outp + ((size_t)w * NF + row) * CC + h * 32);
    #pragma unroll
    for (int d4 = 0; d4 < 8; d4++) {
        float4 a = av[d4];
        ob[d4] = make_float4(a.x * inv, a.y * inv, a.z * inv, a.w * inv);
    }
}

// ---------------------------------------------------------------------------
// Launch
// ---------------------------------------------------------------------------
extern "C" void kernel_launch(void* const* d_in, const int* in_sizes, int n_in,
                              void* d_out, int out_size) {
    (void)in_sizes; (void)n_in; (void)out_size;
    const float* x     = (const float*)d_in[0];
    const float* n1w   = (const float*)d_in[2];
    const float* n1b   = (const float*)d_in[3];
    const float* qkvw  = (const float*)d_in[4];
    const float* qkvb  = (const float*)d_in[5];
    const float* rpb   = (const float*)d_in[6];
    const float* projw = (const float*)d_in[7];
    const float* projb = (const float*)d_in[8];
    const float* n2w   = (const float*)d_in[9];
    const float* n2b   = (const float*)d_in[10];
    const float* fc1w  = (const float*)d_in[11];
    const float* fc1b  = (const float*)d_in[12];
    const float* fc2w  = (const float*)d_in[13];
    const float* fc2b  = (const float*)d_in[14];
    float* out = (float*)d_out;

    float *outf, *x2;
    __nv_bfloat16 *xlnbf, *qkvs, *qkvf, *attnh, *attnbf, *hln, *h1, *w1bf, *w2bf, *wqbf, *wpbf;
    cudaGetSymbolAddress((void**)&xlnbf,  g_xlnbf);
    cudaGetSymbolAddress((void**)&qkvs,   g_qkvs);
    cudaGetSymbolAddress((void**)&qkvf,   g_qkvf);
    cudaGetSymbolAddress((void**)&attnh,  g_attnh);
    cudaGetSymbolAddress((void**)&attnbf, g_attnbf);
    cudaGetSymbolAddress((void**)&outf,   g_outf);
    cudaGetSymbolAddress((void**)&x2,     g_x2);
    cudaGetSymbolAddress((void**)&hln,    g_hln);
    cudaGetSymbolAddress((void**)&h1,     g_h1);
    cudaGetSymbolAddress((void**)&w1bf,   g_w1bf);
    cudaGetSymbolAddress((void**)&w2bf,   g_w2bf);
    cudaGetSymbolAddress((void**)&wqbf,   g_wqbf);
    cudaGetSymbolAddress((void**)&wpbf,   g_wpbf);

    cudaFuncSetAttribute(gemm_bf16<1>, cudaFuncAttributeMaxDynamicSharedMemorySize, BF_SMEM);
    cudaFuncSetAttribute(gemm_bf16<2>, cudaFuncAttributeMaxDynamicSharedMemorySize, BF_SMEM);
    cudaFuncSetAttribute(gemm_bf16<3>, cudaFuncAttributeMaxDynamicSharedMemorySize, BF_SMEM);
    cudaFuncSetAttribute(gemm_bf16<5>, cudaFuncAttributeMaxDynamicSharedMemorySize, BF_SMEM);

    static cudaStream_t s1 = nullptr;
    static cudaEvent_t eF0 = nullptr, eJ0 = nullptr, eF1 = nullptr, eJ1 = nullptr;
    if (!s1) {
        cudaStreamCreateWithFlags(&s1, cudaStreamNonBlocking);
        cudaEventCreateWithFlags(&eF0, cudaEventDisableTiming);
        cudaEventCreateWithFlags(&eJ0, cudaEventDisableTiming);
        cudaEventCreateWithFlags(&eF1, cudaEventDisableTiming);
        cudaEventCreateWithFlags(&eJ1, cudaEventDisableTiming);
    }

    init_dft_kernel<<<5, 256>>>();

    // conv_w on side stream, overlapped with LN1
    cudaEventRecord(eF0, 0);
    cudaStreamWaitEvent(s1, eF0, 0);
    conv_w_kernel<<<1024, 256, 0, s1>>>(fc1w, fc2w, qkvw, projw);
    cudaEventRecord(eJ0, s1);

    // LN1 (+ window partition) -> bf16
    ln_bf16_kernel<<<TOKS / 8, 256>>>(x, n1w, n1b, xlnbf, 1);

    cudaStreamWaitEvent(0, eJ0, 0);

    // spatial qkv + fused spectral DFT (bf16 in/out)
    gemm_bf16<5><<<dim3(768 / 256, TOKS / 128), 512, BF_SMEM>>>(
        xlnbf, wqbf, qkvb, qkvs, TOKS, 768, 256, nullptr, qkvf);

    // fork: spatial attention on s1 || spectral attention on main
    cudaEventRecord(eF1, 0);
    cudaStreamWaitEvent(s1, eF1, 0);
    attn_kernel<<<dim3(NWIN, HEADS), NTOK, 0, s1>>>(qkvs, rpb, attnh);

    attn_spec2_kernel<<<dim3(NWIN / 2, HEADS), 160>>>(qkvf, outf);

    cudaEventRecord(eJ1, s1);
    cudaStreamWaitEvent(0, eJ1, 0);

    // irfft + combine -> bf16 proj input
    ifft_acc_kernel<<<NWIN, 256>>>(outf, attnh, attnbf);

    // proj + window reverse + shortcut -> x2
    gemm_bf16<3><<<dim3(256 / 256, TOKS / 128), 512, BF_SMEM>>>(
        attnbf, wpbf, projb, x2, TOKS, 256, 256, x, nullptr);

    // LN2 -> bf16
    ln_bf16_kernel<<<TOKS / 8, 256>>>(x2, n2w, n2b, hln, 0);

    // fc1 + GELU -> h1 (bf16)
    gemm_bf16<1><<<dim3(1024 / 256, TOKS / 128), 512, BF_SMEM>>>(
        hln, w1bf, fc1b, h1, TOKS, 1024, 256, nullptr, nullptr);

    // fc2 + residual -> out
    gemm_bf16<2><<<dim3(256 / 256, TOKS / 128), 512, BF_SMEM>>>(
        h1, w2bf, fc2b, out, TOKS, 256, 1024, x2, nullptr);
}

// round 15
// speedup vs baseline: 1.0064x; 1.0064x over previous
#include <cuda_runtime.h>
#include <cuda_bf16.h>
#include <math.h>
#include <stdint.h>

// ---------------------------------------------------------------------------
// Problem constants
// ---------------------------------------------------------------------------
#define CC      256
#define WS      8
#define NTOK    64
#define NF      66
#define HEADS   8
#define HD      32
#define NWIN    2048
#define TOKS    131072
#define SCALE   0.17677669529663687f

// ---------------------------------------------------------------------------
// Scratch
// ---------------------------------------------------------------------------
__device__ __nv_bfloat16 g_xlnbf[ (size_t)TOKS * CC ];
__device__ __nv_bfloat16 g_qkvs[ (size_t)NWIN * NTOK * 3 * CC ];
__device__ __nv_bfloat16 g_qkvf[ (size_t)NWIN * NF * 3 * CC ];
__device__ __nv_bfloat16 g_attnh[ (size_t)NWIN * NTOK * CC ];
__device__ __nv_bfloat16 g_attnbf[ (size_t)NWIN * NTOK * CC ];
__device__ float g_outf[ (size_t)NWIN * NF   * CC ];
__device__ float g_x2  [ (size_t)TOKS * CC ];
__device__ __nv_bfloat16 g_hln[ (size_t)TOKS * CC ];
__device__ __nv_bfloat16 g_h1 [ (size_t)TOKS * 4 * CC ];
__device__ __nv_bfloat16 g_w1bf[ 1024 * 256 ];
__device__ __nv_bfloat16 g_w2bf[ 256 * 1024 ];
__device__ __nv_bfloat16 g_wqbf[ 768 * 256 ];
__device__ __nv_bfloat16 g_wpbf[ 256 * 256 ];
__device__ float g_Fc[ 33 * 34 ];
__device__ float g_Fs[ 33 * 34 ];
__device__ float g_Ic[ 33 * 34 ];
__device__ float g_Is[ 33 * 34 ];

// ---------------------------------------------------------------------------
// Helpers
// ---------------------------------------------------------------------------
__device__ __forceinline__ uint32_t smem_u32(const void* p) {
    uint32_t a;
    asm("{ .reg .u64 t; cvta.to.shared.u64 t, %1; cvt.u32.u64 %0, t; }"
        : "=r"(a) : "l"(p));
    return a;
}

#define CP_ASYNC16(dst_u32, src_ptr) \
    asm volatile("cp.async.cg.shared.global [%0], [%1], 16;" \
        :: "r"(dst_u32), "l"(src_ptr))
#define CP_COMMIT() asm volatile("cp.async.commit_group;")
#define CP_WAIT1()  asm volatile("cp.async.wait_group 1;")
#define CP_WAIT0()  asm volatile("cp.async.wait_group 0;")

__device__ __forceinline__ void mma16n8k16bf(float* c, const uint32_t* a,
                                             const uint32_t* b) {
    asm volatile(
        "mma.sync.aligned.m16n8k16.row.col.f32.bf16.bf16.f32 "
        "{%0,%1,%2,%3}, {%4,%5,%6,%7}, {%8,%9}, {%0,%1,%2,%3};"
        : "+f"(c[0]), "+f"(c[1]), "+f"(c[2]), "+f"(c[3])
        : "r"(a[0]), "r"(a[1]), "r"(a[2]), "r"(a[3]), "r"(b[0]), "r"(b[1]));
}

__device__ __forceinline__ int win2pix(int t) {
    int b   = t >> 16;
    int rem = t & 65535;
    int wl  = rem >> 6;
    int n   = rem & 63;
    int wh  = wl >> 5, ww = wl & 31;
    int i   = n >> 3,  j  = n & 7;
    return (b * 256 + wh * 8 + i) * 256 + (ww * 8 + j);
}

__device__ __forceinline__ float dot4(float4 a, float4 b) {
    return a.x * b.x + a.y * b.y + a.z * b.z + a.w * b.w;
}

__device__ __forceinline__ void bf8_to_f8(uint4 r, float* o) {
    const __nv_bfloat162* p = (const __nv_bfloat162*)&r;
    #pragma unroll
    for (int i = 0; i < 4; i++) {
        float2 f = __bfloat1622float2(p[i]);
        o[2 * i] = f.x; o[2 * i + 1] = f.y;
    }
}

// ---------------------------------------------------------------------------
// DFT matrix init
// ---------------------------------------------------------------------------
__global__ void init_dft_kernel() {
    int i = blockIdx.x * blockDim.x + threadIdx.x;
    if (i < 33 * 34) {
        int r = i / 34, c = i % 34;
        float fc = 0.f, fs = 0.f, ic = 0.f, is = 0.f;
        if (c < 33) {
            float cs = cospif((float)(r * c) / 32.0f);
            float sn = sinpif((float)(r * c) / 32.0f);
            fc = 0.125f * cs;
            fs = -0.125f * sn;
            if (c == 0)       ic = 0.125f;
            else if (c == 32) ic = 0.125f * cospif((float)r);
            else              ic = 0.25f * cs;
            is = -0.25f * sn;
        }
        g_Fc[i] = fc; g_Fs[i] = fs; g_Ic[i] = ic; g_Is[i] = is;
    }
}

__global__ void conv_w_kernel(const float* __restrict__ w1,
                              const float* __restrict__ w2,
                              const float* __restrict__ wq,
                              const float* __restrict__ wp) {
    int i = blockIdx.x * blockDim.x + threadIdx.x;
    if (i < 1024 * 256) {
        g_w1bf[i] = __float2bfloat16_rn(w1[i]);
        g_w2bf[i] = __float2bfloat16_rn(w2[i]);
    }
    if (i < 768 * 256)  g_wqbf[i] = __float2bfloat16_rn(wq[i]);
    if (i < 256 * 256)  g_wpbf[i] = __float2bfloat16_rn(wp[i]);
}

// ---------------------------------------------------------------------------
// LayerNorm -> bf16, warp-per-row
// ---------------------------------------------------------------------------
__global__ __launch_bounds__(256)
void ln_bf16_kernel(const float* __restrict__ xin,
                    const float* __restrict__ w,
                    const float* __restrict__ b,
                    __nv_bfloat16* __restrict__ out, int winmap) {
    int warp = threadIdx.x >> 5, lane = threadIdx.x & 31;
    int t = blockIdx.x * 8 + warp;
    int rin = winmap ? win2pix(t) : t;
    const float4* src = (const float4*)(xin + (size_t)rin * CC) + lane * 2;
    float4 v0 = src[0], v1 = src[1];
    float s = v0.x + v0.y + v0.z + v0.w + v1.x + v1.y + v1.z + v1.w;
    float sq = v0.x * v0.x + v0.y * v0.y + v0.z * v0.z + v0.w * v0.w
             + v1.x * v1.x + v1.y * v1.y + v1.z * v1.z + v1.w * v1.w;
    #pragma unroll
    for (int o = 16; o; o >>= 1) {
        s  += __shfl_xor_sync(0xffffffffu, s,  o);
        sq += __shfl_xor_sync(0xffffffffu, sq, o);
    }
    float mean = s * (1.0f / CC);
    float var  = sq * (1.0f / CC) - mean * mean;
    float rstd = rsqrtf(var + 1e-5f);
    const float4* wp4 = (const float4*)w + lane * 2;
    const float4* bp4 = (const float4*)b + lane * 2;
    float4 w0 = wp4[0], w1 = wp4[1];
    float4 b0 = bp4[0], b1 = bp4[1];
    __nv_bfloat162 o4[4];
    o4[0] = __floats2bfloat162_rn((v0.x - mean) * rstd * w0.x + b0.x,
                                  (v0.y - mean) * rstd * w0.y + b0.y);
    o4[1] = __floats2bfloat162_rn((v0.z - mean) * rstd * w0.z + b0.z,
                                  (v0.w - mean) * rstd * w0.w + b0.w);
    o4[2] = __floats2bfloat162_rn((v1.x - mean) * rstd * w1.x + b1.x,
                                  (v1.y - mean) * rstd * w1.y + b1.y);
    o4[3] = __floats2bfloat162_rn((v1.z - mean) * rstd * w1.z + b1.z,
                                  (v1.w - mean) * rstd * w1.w + b1.w);
    *(uint4*)(out + (size_t)t * CC + lane * 8) = *(uint4*)o4;
}

// ---------------------------------------------------------------------------
// bf16 mma.sync GEMM, 512 threads / 16 warps, 128x256 tile, warp 64x32.
// EPI: 1 GELU->bf16; 2 +res fp32; 3 winrev+res fp32; 4 plain bf16
// ---------------------------------------------------------------------------
#define HPAD 72
#define A_STG_H (128 * HPAD)
#define B_STG_H (256 * HPAD)
#define BF_SMEM (3 * (A_STG_H + B_STG_H) * 2)

template<int EPI>
__global__ __launch_bounds__(512, 1)
void gemm_bf16(const __nv_bfloat16* __restrict__ A,
               const __nv_bfloat16* __restrict__ W,
               const float* __restrict__ bias, void* __restrict__ Cv,
               int M, int N, int K, const float* __restrict__ res) {
    extern __shared__ char smc[];
    __nv_bfloat16* AsBase = (__nv_bfloat16*)smc;
    __nv_bfloat16* BsBase = AsBase + 3 * A_STG_H;
    uint32_t sA = smem_u32(AsBase);
    uint32_t sB = smem_u32(BsBase);

    int tid = threadIdx.x;
    int m0 = blockIdx.y * 128, n0 = blockIdx.x * 256;
    int wid = tid >> 5, lane = tid & 31;
    int wm = (wid & 1) * 64, wn = (wid >> 1) * 32;
    int grp = lane >> 2, tg = lane & 3;

    float acc[4][4][4];
    #pragma unroll
    for (int a = 0; a < 4; a++)
        #pragma unroll
        for (int b = 0; b < 4; b++)
            #pragma unroll
            for (int c = 0; c < 4; c++) acc[a][b][c] = 0.f;

    const int NC = K / 64;

    #pragma unroll
    for (int pc = 0; pc < 2; pc++) {
        #pragma unroll
        for (int t = 0; t < 2; t++) {
            int idx = tid + t * 512;
            int row = idx >> 3, q = idx & 7;
            CP_ASYNC16(sA + (uint32_t)(pc * A_STG_H + row * HPAD + q * 8) * 2u,
                       A + (size_t)(m0 + row) * K + pc * 64 + q * 8);
        }
        #pragma unroll
        for (int t = 0; t < 4; t++) {
            int idx = tid + t * 512;
            int row = idx >> 3, q = idx & 7;
            CP_ASYNC16(sB + (uint32_t)(pc * B_STG_H + row * HPAD + q * 8) * 2u,
                       W + (size_t)(n0 + row) * K + pc * 64 + q * 8);
        }
        CP_COMMIT();
    }

    for (int i = 0; i < NC; i++) {
        if (i + 1 < NC) CP_WAIT1(); else CP_WAIT0();
        __syncthreads();
        if (i + 2 < NC) {
            int st = (i + 2) % 3;
            #pragma unroll
            for (int t = 0; t < 2; t++) {
                int idx = tid + t * 512;
                int row = idx >> 3, q = idx & 7;
                CP_ASYNC16(sA + (uint32_t)(st * A_STG_H + row * HPAD + q * 8) * 2u,
                           A + (size_t)(m0 + row) * K + (i + 2) * 64 + q * 8);
            }
            #pragma unroll
            for (int t = 0; t < 4; t++) {
                int idx = tid + t * 512;
                int row = idx >> 3, q = idx & 7;
                CP_ASYNC16(sB + (uint32_t)(st * B_STG_H + row * HPAD + q * 8) * 2u,
                           W + (size_t)(n0 + row) * K + (i + 2) * 64 + q * 8);
            }
            CP_COMMIT();
        }

        const __nv_bfloat16* As = AsBase + (i % 3) * A_STG_H;
        const __nv_bfloat16* Bs = BsBase + (i % 3) * B_STG_H;
        #pragma unroll
        for (int ks = 0; ks < 4; ks++) {
            uint32_t af[4][4];
            uint32_t bf[4][2];
            #pragma unroll
            for (int mi = 0; mi < 4; mi++) {
                int r = wm + mi * 16 + grp;
                af[mi][0] = *(const uint32_t*)(As + r * HPAD + ks * 16 + tg * 2);
                af[mi][1] = *(const uint32_t*)(As + (r + 8) * HPAD + ks * 16 + tg * 2);
                af[mi][2] = *(const uint32_t*)(As + r * HPAD + ks * 16 + tg * 2 + 8);
                af[mi][3] = *(const uint32_t*)(As + (r + 8) * HPAD + ks * 16 + tg * 2 + 8);
            }
            #pragma unroll
            for (int ni = 0; ni < 4; ni++) {
                int r = wn + ni * 8 + grp;
                bf[ni][0] = *(const uint32_t*)(Bs + r * HPAD + ks * 16 + tg * 2);
                bf[ni][1] = *(const uint32_t*)(Bs + r * HPAD + ks * 16 + tg * 2 + 8);
            }
            #pragma unroll
            for (int mi = 0; mi < 4; mi++)
                #pragma unroll
                for (int ni = 0; ni < 4; ni++)
                    mma16n8k16bf(acc[mi][ni], af[mi], bf[ni]);
        }
    }

    #pragma unroll
    for (int mi = 0; mi < 4; mi++) {
        #pragma unroll
        for (int half = 0; half < 2; half++) {
            int m = m0 + wm + mi * 16 + grp + half * 8;
            size_t orow = (EPI == 3) ? (size_t)win2pix(m) * N : (size_t)m * N;
            #pragma unroll
            for (int ni = 0; ni < 4; ni++) {
                int n = n0 + wn + ni * 8 + tg * 2;
                float vx = acc[mi][ni][half * 2 + 0] + bias[n];
                float vy = acc[mi][ni][half * 2 + 1] + bias[n + 1];
                if (EPI == 1) {
                    vx = 0.5f * vx * (1.0f + erff(vx * 0.7071067811865476f));
                    vy = 0.5f * vy * (1.0f + erff(vy * 0.7071067811865476f));
                    ((__nv_bfloat162*)Cv)[(orow + n) >> 1] = __floats2bfloat162_rn(vx, vy);
                } else if (EPI == 4) {
                    ((__nv_bfloat162*)Cv)[(orow + n) >> 1] = __floats2bfloat162_rn(vx, vy);
                } else {
                    vx += res[orow + n];
                    vy += res[orow + n + 1];
                    *(float2*)((float*)Cv + orow + n) = make_float2(vx, vy);
                }
            }
        }
    }
}

// ---------------------------------------------------------------------------
// Fused spectral qkv (bf16 in/out) with cos/sin symmetry
// ---------------------------------------------------------------------------
__global__ __launch_bounds__(256)
void spec_qkv_kernel(const __nv_bfloat16* __restrict__ qkvs,
                     const float* __restrict__ qkvb,
                     __nv_bfloat16* __restrict__ qkvf) {
    __shared__ float Fc[33 * 34];
    __shared__ float Fs[33 * 34];
    int w = blockIdx.x;
    int tid = threadIdx.x;
    int ch = blockIdx.y * 256 + tid;
    for (int m = tid; m < 33 * 34; m += 256) { Fc[m] = g_Fc[m]; Fs[m] = g_Fs[m]; }

    float e[33], o[32];
    const __nv_bfloat16* src = qkvs + (size_t)w * NTOK * 768 + ch;
    e[0]  = __bfloat162float(src[0]);
    e[32] = __bfloat162float(src[(size_t)32 * 768]);
    #pragma unroll
    for (int n = 1; n < 32; n++) {
        float a = __bfloat162float(src[(size_t)n * 768]);
        float b = __bfloat162float(src[(size_t)(64 - n) * 768]);
        e[n] = a + b;
        o[n] = a - b;
    }
    __syncthreads();

    float bb = qkvb[ch];
    __nv_bfloat16* dst = qkvf + (size_t)w * NF * 768 + ch;

    #pragma unroll 1
    for (int f = 0; f < 32; f += 2) {
        const float* R0 = Fc + f * 34;
        const float* R1 = R0 + 34;
        float s0 = 0.f, s0b = 0.f, s1 = 0.f, s1b = 0.f;
        #pragma unroll
        for (int n = 0; n < 32; n += 2) {
            s0  += R0[n] * e[n];     s0b += R0[n + 1] * e[n + 1];
            s1  += R1[n] * e[n];     s1b += R1[n + 1] * e[n + 1];
        }
        s0 += R0[32] * e[32];
        s1 += R1[32] * e[32];
        dst[(size_t)f * 768]       = __float2bfloat16_rn(s0 + s0b + ((f == 0) ? -7.0f * bb : bb));
        dst[(size_t)(f + 1) * 768] = __float2bfloat16_rn(s1 + s1b + bb);
    }
    {
        const float* R0 = Fc + 32 * 34;
        float s0 = 0.f, s0b = 0.f;
        #pragma unroll
        for (int n = 0; n < 32; n += 2) {
            s0 += R0[n] * e[n]; s0b += R0[n + 1] * e[n + 1];
        }
        s0 += R0[32] * e[32];
        dst[(size_t)32 * 768] = __float2bfloat16_rn(s0 + s0b + bb);
    }

    dst[(size_t)33 * 768] = __float2bfloat16_rn(bb);
    dst[(size_t)65 * 768] = __float2bfloat16_rn(bb);

    #pragma unroll 1
    for (int f = 1; f < 31; f += 2) {
        const float* R0 = Fs + f * 34;
        const float* R1 = R0 + 34;
        float s0 = 0.f, s0b = 0.f, s1 = 0.f, s1b = 0.f;
        #pragma unroll
        for (int n = 1; n < 31; n += 2) {
            s0  += R0[n] * o[n];     s0b += R0[n + 1] * o[n + 1];
            s1  += R1[n] * o[n];     s1b += R1[n + 1] * o[n + 1];
        }
        s0 += R0[31] * o[31];
        s1 += R1[31] * o[31];
        dst[(size_t)(33 + f) * 768] = __float2bfloat16_rn(s0 + s0b + bb);
        dst[(size_t)(34 + f) * 768] = __float2bfloat16_rn(s1 + s1b + bb);
    }
    {
        const float* R0 = Fs + 31 * 34;
        float s0 = 0.f, s0b = 0.f;
        #pragma unroll
        for (int n = 1; n < 31; n += 2) {
            s0 += R0[n] * o[n]; s0b += R0[n + 1] * o[n + 1];
        }
        s0 += R0[31] * o[31];
        dst[(size_t)64 * 768] = __float2bfloat16_rn(s0 + s0b + bb);
    }
}

// ---------------------------------------------------------------------------
// Inverse rfft: attnbf = bf16(attn(bf16) + irfft(outf))
// ---------------------------------------------------------------------------
__global__ __launch_bounds__(256)
void ifft_acc_kernel(const float* __restrict__ outf,
                     const __nv_bfloat16* __restrict__ attn,
                     __nv_bfloat16* __restrict__ attnbf) {
    __shared__ float Ic[33 * 34];
    __shared__ float Is[33 * 34];
    int w = blockIdx.x;
    int c = threadIdx.x;
    for (int m = c; m < 33 * 34; m += 256) { Ic[m] = g_Ic[m]; Is[m] = g_Is[m]; }

    float fr[NF];
    const float* src = outf + (size_t)w * NF * CC + c;
    #pragma unroll 11
    for (int r = 0; r < NF; r++) fr[r] = src[(size_t)r * CC];
    __syncthreads();

    const __nv_bfloat16* ain = attn + (size_t)w * NTOK * CC + c;
    __nv_bfloat16* dst = attnbf + (size_t)w * NTOK * CC + c;
    #pragma unroll 1
    for (int n = 0; n < 32; n += 2) {
        const float* C0 = Ic + n * 34;
        const float* C1 = C0 + 34;
        const float* S0 = Is + n * 34;
        const float* S1 = S0 + 34;
        float a0 = 0.f, a0b = 0.f, a1 = 0.f, a1b = 0.f;
        #pragma unroll
        for (int r = 0; r < 32; r += 2) {
            a0  += C0[r] * fr[r];     a0b += C0[r + 1] * fr[r + 1];
            a1  += C1[r] * fr[r];     a1b += C1[r + 1] * fr[r + 1];
        }
        a0 += C0[32] * fr[32];
        a1 += C1[32] * fr[32];
        float b0 = 0.f, b0b = 0.f, b1 = 0.f, b1b = 0.f;
        #pragma unroll
        for (int r = 1; r < 31; r += 2) {
            b0  += S0[r] * fr[33 + r];     b0b += S0[r + 1] * fr[34 + r];
            b1  += S1[r] * fr[33 + r];     b1b += S1[r + 1] * fr[34 + r];
        }
        b0 += S0[31] * fr[64];
        b1 += S1[31] * fr[64];
        float A0 = a0 + a0b, B0 = b0 + b0b;
        float A1 = a1 + a1b, B1 = b1 + b1b;
        dst[(size_t)n * CC] =
            __float2bfloat16_rn(__bfloat162float(ain[(size_t)n * CC]) + A0 + B0);
        if (n >= 1)
            dst[(size_t)(64 - n) * CC] =
                __float2bfloat16_rn(__bfloat162float(ain[(size_t)(64 - n) * CC]) + A0 - B0);
        dst[(size_t)(n + 1) * CC] =
            __float2bfloat16_rn(__bfloat162float(ain[(size_t)(n + 1) * CC]) + A1 + B1);
        dst[(size_t)(63 - n) * CC] =
            __float2bfloat16_rn(__bfloat162float(ain[(size_t)(63 - n) * CC]) + A1 - B1);
    }
    {
        const float* C0 = Ic + 32 * 34;
        float a0 = 0.f, a0b = 0.f;
        #pragma unroll
        for (int r = 0; r < 32; r += 2) {
            a0 += C0[r] * fr[r]; a0b += C0[r + 1] * fr[r + 1];
        }
        a0 += C0[32] * fr[32];
        dst[(size_t)32 * CC] =
            __float2bfloat16_rn(__bfloat162float(ain[(size_t)32 * CC]) + a0 + a0b);
    }
}

// ---------------------------------------------------------------------------
// Spatial window attention, bf16 in/out
// ---------------------------------------------------------------------------
__global__ void attn_kernel(const __nv_bfloat16* __restrict__ qkv,
                            const float* __restrict__ rpb,
                            __nv_bfloat16* __restrict__ outp) {
    const int NT = NTOK;
    __shared__ float ks[NT][36];
    __shared__ float vs[NT][36];
    __shared__ float ss[NT][65];
    __shared__ float rpb_s[225];

    int w = blockIdx.x, h = blockIdx.y;
    int row = threadIdx.x;

    float4 qv[8];
    {
        const uint4* base = (const uint4*)(qkv + ((size_t)w * NT + row) * 768 + h * 32);
        #pragma unroll
        for (int i = 0; i < 4; i++) {
            float qf[8];
            bf8_to_f8(base[i], qf);
            qv[2 * i]     = make_float4(qf[0] * SCALE, qf[1] * SCALE, qf[2] * SCALE, qf[3] * SCALE);
            qv[2 * i + 1] = make_float4(qf[4] * SCALE, qf[5] * SCALE, qf[6] * SCALE, qf[7] * SCALE);
            bf8_to_f8(base[32 + i], &ks[row][i * 8]);
            bf8_to_f8(base[64 + i], &vs[row][i * 8]);
        }
    }
    for (int m = row; m < 225; m += NT) rpb_s[m] = rpb[m * HEADS + h];
    __syncthreads();

    int yi = row >> 3, xi = row & 7;
    float mx = -1e30f;
    for (int j = 0; j < NT; j += 4) {
        const float4* k0 = (const float4*)ks[j + 0];
        const float4* k1 = (const float4*)ks[j + 1];
        const float4* k2 = (const float4*)ks[j + 2];
        const float4* k3 = (const float4*)ks[j + 3];
        float s0 = 0.f, s1 = 0.f, s2 = 0.f, s3 = 0.f;
        #pragma unroll
        for (int d4 = 0; d4 < 8; d4++) {
            float4 q = qv[d4];
            s0 += dot4(q, k0[d4]);
            s1 += dot4(q, k1[d4]);
            s2 += dot4(q, k2[d4]);
            s3 += dot4(q, k3[d4]);
        }
        int bi = (yi + 7) * 15 + (xi + 7);
        s0 += rpb_s[bi - ((j + 0) >> 3) * 15 - ((j + 0) & 7)];
        s1 += rpb_s[bi - ((j + 1) >> 3) * 15 - ((j + 1) & 7)];
        s2 += rpb_s[bi - ((j + 2) >> 3) * 15 - ((j + 2) & 7)];
        s3 += rpb_s[bi - ((j + 3) >> 3) * 15 - ((j + 3) & 7)];
        ss[row][j + 0] = s0; ss[row][j + 1] = s1;
        ss[row][j + 2] = s2; ss[row][j + 3] = s3;
        mx = fmaxf(mx, fmaxf(fmaxf(s0, s1), fmaxf(s2, s3)));
    }

    float sum0 = 0.f, sum1 = 0.f;
    for (int jj = 0; jj < NT; jj += 2) {
        float e0 = __expf(ss[row][jj] - mx);
        float e1 = __expf(ss[row][jj + 1] - mx);
        ss[row][jj] = e0; ss[row][jj + 1] = e1;
        sum0 += e0; sum1 += e1;
    }
    float inv = 1.0f / (sum0 + sum1);

    float4 av[8];
    #pragma unroll
    for (int d4 = 0; d4 < 8; d4++) av[d4] = make_float4(0.f, 0.f, 0.f, 0.f);
    for (int jj = 0; jj < NT; jj += 2) {
        float p0 = ss[row][jj];
        float p1 = ss[row][jj + 1];
        const float4* v0 = (const float4*)vs[jj];
        const float4* v1 = (const float4*)vs[jj + 1];
        #pragma unroll
        for (int d4 = 0; d4 < 8; d4++) {
            float4 a = av[d4];
            float4 x0 = v0[d4], x1 = v1[d4];
            a.x += p0 * x0.x + p1 * x1.x;
            a.y += p0 * x0.y + p1 * x1.y;
            a.z += p0 * x0.z + p1 * x1.z;
            a.w += p0 * x0.w + p1 * x1.w;
            av[d4] = a;
        }
    }

    __nv_bfloat162* ob = (__nv_bfloat162*)(outp + ((size_t)w * NT + row) * CC + h * 32);
    #pragma unroll
    for (int d4 = 0; d4 < 8; d4++) {
        float4 a = av[d4];
        ob[2 * d4]     = __floats2bfloat162_rn(a.x * inv, a.y * inv);
        ob[2 * d4 + 1] = __floats2bfloat162_rn(a.z * inv, a.w * inv);
    }
}

// ---------------------------------------------------------------------------
// Spectral attention: 2 windows per block, bf16 input
// ---------------------------------------------------------------------------
__global__ __launch_bounds__(160)
void attn_spec2_kernel(const __nv_bfloat16* __restrict__ qkv,
                       float* __restrict__ outp) {
    __shared__ float ks[2][NF][36];
    __shared__ float vs[2][NF][36];
    __shared__ float ss[2][NF][67];

    int w2 = blockIdx.x, h = blockIdx.y;
    int tid = threadIdx.x;
    int sub = tid / NF;
    int row = tid % NF;
    bool act = tid < 2 * NF;
    int w = w2 * 2 + sub;

    float4 qv[8];
    if (act) {
        const uint4* base = (const uint4*)(qkv + ((size_t)w * NF + row) * 768 + h * 32);
        #pragma unroll
        for (int i = 0; i < 4; i++) {
            float qf[8];
            bf8_to_f8(base[i], qf);
            qv[2 * i]     = make_float4(qf[0] * SCALE, qf[1] * SCALE, qf[2] * SCALE, qf[3] * SCALE);
            qv[2 * i + 1] = make_float4(qf[4] * SCALE, qf[5] * SCALE, qf[6] * SCALE, qf[7] * SCALE);
            bf8_to_f8(base[32 + i], &ks[sub][row][i * 8]);
            bf8_to_f8(base[64 + i], &vs[sub][row][i * 8]);
        }
    }
    __syncthreads();
    if (!act) return;

    float mx = -1e30f;
    int j = 0;
    for (; j + 3 < NF; j += 4) {
        const float4* k0 = (const float4*)ks[sub][j + 0];
        const float4* k1 = (const float4*)ks[sub][j + 1];
        const float4* k2 = (const float4*)ks[sub][j + 2];
        const float4* k3 = (const float4*)ks[sub][j + 3];
        float s0 = 0.f, s1 = 0.f, s2 = 0.f, s3 = 0.f;
        #pragma unroll
        for (int d4 = 0; d4 < 8; d4++) {
            float4 q = qv[d4];
            s0 += dot4(q, k0[d4]);
            s1 += dot4(q, k1[d4]);
            s2 += dot4(q, k2[d4]);
            s3 += dot4(q, k3[d4]);
        }
        ss[sub][row][j + 0] = s0; ss[sub][row][j + 1] = s1;
        ss[sub][row][j + 2] = s2; ss[sub][row][j + 3] = s3;
        mx = fmaxf(mx, fmaxf(fmaxf(s0, s1), fmaxf(s2, s3)));
    }
    for (; j < NF; j++) {
        const float4* k0 = (const float4*)ks[sub][j];
        float s0 = 0.f;
        #pragma unroll
        for (int d4 = 0; d4 < 8; d4++) s0 += dot4(qv[d4], k0[d4]);
        ss[sub][row][j] = s0;
        mx = fmaxf(mx, s0);
    }

    float sum0 = 0.f, sum1 = 0.f;
    for (int jj = 0; jj + 1 < NF; jj += 2) {
        float e0 = __expf(ss[sub][row][jj] - mx);
        float e1 = __expf(ss[sub][row][jj + 1] - mx);
        ss[sub][row][jj] = e0; ss[sub][row][jj + 1] = e1;
        sum0 += e0; sum1 += e1;
    }
    float inv = 1.0f / (sum0 + sum1);

    float4 av[8];
    #pragma unroll
    for (int d4 = 0; d4 < 8; d4++) av[d4] = make_float4(0.f, 0.f, 0.f, 0.f);
    for (int jj = 0; jj + 1 < NF; jj += 2) {
        float p0 = ss[sub][row][jj];
        float p1 = ss[sub][row][jj + 1];
        const float4* v0 = (const float4*)vs[sub][jj];
        const float4* v1 = (const float4*)vs[sub][jj + 1];
        #pragma unroll
        for (int d4 = 0; d4 < 8; d4++) {
            float4 a = av[d4];
            float4 x0 = v0[d4], x1 = v1[d4];
            a.x += p0 * x0.x + p1 * x1.x;
            a.y += p0 * x0.y + p1 * x1.y;
            a.z += p0 * x0.z + p1 * x1.z;
            a.w += p0 * x0.w + p1 * x1.w;
            av[d4] = a;
        }
    }

    float4* ob = (float4*)(outp + ((size_t)w * NF + row) * CC + h * 32);
    #pragma unroll
    for (int d4 = 0; d4 < 8; d4++) {
        float4 a = av[d4];
        ob[d4] = make_float4(a.x * inv, a.y * inv, a.z * inv, a.w * inv);
    }
}

// ---------------------------------------------------------------------------
// Launch
// ---------------------------------------------------------------------------
extern "C" void kernel_launch(void* const* d_in, const int* in_sizes, int n_in,
                              void* d_out, int out_size) {
    (void)in_sizes; (void)n_in; (void)out_size;
    const float* x     = (const float*)d_in[0];
    const float* n1w   = (const float*)d_in[2];
    const float* n1b   = (const float*)d_in[3];
    const float* qkvw  = (const float*)d_in[4];
    const float* qkvb  = (const float*)d_in[5];
    const float* rpb   = (const float*)d_in[6];
    const float* projw = (const float*)d_in[7];
    const float* projb = (const float*)d_in[8];
    const float* n2w   = (const float*)d_in[9];
    const float* n2b   = (const float*)d_in[10];
    const float* fc1w  = (const float*)d_in[11];
    const float* fc1b  = (const float*)d_in[12];
    const float* fc2w  = (const float*)d_in[13];
    const float* fc2b  = (const float*)d_in[14];
    float* out = (float*)d_out;

    float *outf, *x2;
    __nv_bfloat16 *xlnbf, *qkvs, *qkvf, *attnh, *attnbf, *hln, *h1, *w1bf, *w2bf, *wqbf, *wpbf;
    cudaGetSymbolAddress((void**)&xlnbf,  g_xlnbf);
    cudaGetSymbolAddress((void**)&qkvs,   g_qkvs);
    cudaGetSymbolAddress((void**)&qkvf,   g_qkvf);
    cudaGetSymbolAddress((void**)&attnh,  g_attnh);
    cudaGetSymbolAddress((void**)&attnbf, g_attnbf);
    cudaGetSymbolAddress((void**)&outf,   g_outf);
    cudaGetSymbolAddress((void**)&x2,     g_x2);
    cudaGetSymbolAddress((void**)&hln,    g_hln);
    cudaGetSymbolAddress((void**)&h1,     g_h1);
    cudaGetSymbolAddress((void**)&w1bf,   g_w1bf);
    cudaGetSymbolAddress((void**)&w2bf,   g_w2bf);
    cudaGetSymbolAddress((void**)&wqbf,   g_wqbf);
    cudaGetSymbolAddress((void**)&wpbf,   g_wpbf);

    cudaFuncSetAttribute(gemm_bf16<1>, cudaFuncAttributeMaxDynamicSharedMemorySize, BF_SMEM);
    cudaFuncSetAttribute(gemm_bf16<2>, cudaFuncAttributeMaxDynamicSharedMemorySize, BF_SMEM);
    cudaFuncSetAttribute(gemm_bf16<3>, cudaFuncAttributeMaxDynamicSharedMemorySize, BF_SMEM);
    cudaFuncSetAttribute(gemm_bf16<4>, cudaFuncAttributeMaxDynamicSharedMemorySize, BF_SMEM);

    static cudaStream_t s1 = nullptr;
    static cudaEvent_t eF0 = nullptr, eJ0 = nullptr, eF1 = nullptr, eJ1 = nullptr;
    if (!s1) {
        cudaStreamCreateWithFlags(&s1, cudaStreamNonBlocking);
        cudaEventCreateWithFlags(&eF0, cudaEventDisableTiming);
        cudaEventCreateWithFlags(&eJ0, cudaEventDisableTiming);
        cudaEventCreateWithFlags(&eF1, cudaEventDisableTiming);
        cudaEventCreateWithFlags(&eJ1, cudaEventDisableTiming);
    }

    init_dft_kernel<<<5, 256>>>();

    // conv_w on side stream, overlapped with LN1
    cudaEventRecord(eF0, 0);
    cudaStreamWaitEvent(s1, eF0, 0);
    conv_w_kernel<<<1024, 256, 0, s1>>>(fc1w, fc2w, qkvw, projw);
    cudaEventRecord(eJ0, s1);

    // LN1 (+ window partition) -> bf16
    ln_bf16_kernel<<<TOKS / 8, 256>>>(x, n1w, n1b, xlnbf, 1);

    cudaStreamWaitEvent(0, eJ0, 0);

    // spatial qkv (bf16 in/out)
    gemm_bf16<4><<<dim3(768 / 256, TOKS / 128), 512, BF_SMEM>>>(
        xlnbf, wqbf, qkvb, qkvs, TOKS, 768, 256, nullptr);

    // fork: spatial attention on s1 || spectral chain on main
    cudaEventRecord(eF1, 0);
    cudaStreamWaitEvent(s1, eF1, 0);
    attn_kernel<<<dim3(NWIN, HEADS), NTOK, 0, s1>>>(qkvs, rpb, attnh);

    spec_qkv_kernel<<<dim3(NWIN, 3), 256>>>(qkvs, qkvb, qkvf);
    attn_spec2_kernel<<<dim3(NWIN / 2, HEADS), 160>>>(qkvf, outf);

    cudaEventRecord(eJ1, s1);
    cudaStreamWaitEvent(0, eJ1, 0);

    // irfft + combine -> bf16 proj input
    ifft_acc_kernel<<<NWIN, 256>>>(outf, attnh, attnbf);

    // proj + window reverse + shortcut -> x2
    gemm_bf16<3><<<dim3(256 / 256, TOKS / 128), 512, BF_SMEM>>>(
        attnbf, wpbf, projb, x2, TOKS, 256, 256, x);

    // LN2 -> bf16
    ln_bf16_kernel<<<TOKS / 8, 256>>>(x2, n2w, n2b, hln, 0);

    // fc1 + GELU -> h1 (bf16)
    gemm_bf16<1><<<dim3(1024 / 256, TOKS / 128), 512, BF_SMEM>>>(
        hln, w1bf, fc1b, h1, TOKS, 1024, 256, nullptr);

    // fc2 + residual -> out
    gemm_bf16<2><<<dim3(256 / 256, TOKS / 128), 512, BF_SMEM>>>(
        h1, w2bf, fc2b, out, TOKS, 256, 1024, x2);
}

// round 16
// speedup vs baseline: 1.0148x; 1.0083x over previous
#include <cuda_runtime.h>
#include <cuda_bf16.h>
#include <cuda_fp16.h>
#include <math.h>
#include <stdint.h>

// ---------------------------------------------------------------------------
// Problem constants
// ---------------------------------------------------------------------------
#define CC      256
#define WS      8
#define NTOK    64
#define NF      66
#define HEADS   8
#define HD      32
#define NWIN    2048
#define TOKS    131072
#define SCALE   0.17677669529663687f

// ---------------------------------------------------------------------------
// Scratch
// ---------------------------------------------------------------------------
__device__ __nv_bfloat16 g_xlnbf[ (size_t)TOKS * CC ];
__device__ __nv_bfloat16 g_qkvs[ (size_t)NWIN * NTOK * 3 * CC ];
__device__ __nv_bfloat16 g_qkvf[ (size_t)NWIN * NF * 3 * CC ];
__device__ __nv_bfloat16 g_attnh[ (size_t)NWIN * NTOK * CC ];
__device__ __nv_bfloat16 g_attnbf[ (size_t)NWIN * NTOK * CC ];
__device__ float g_outf[ (size_t)NWIN * NF   * CC ];
__device__ float g_x2  [ (size_t)TOKS * CC ];
__device__ __nv_bfloat16 g_hln[ (size_t)TOKS * CC ];
__device__ __nv_bfloat16 g_h1 [ (size_t)TOKS * 4 * CC ];
__device__ __nv_bfloat16 g_w1bf[ 1024 * 256 ];
__device__ __nv_bfloat16 g_w2bf[ 256 * 1024 ];
__device__ __nv_bfloat16 g_wqbf[ 768 * 256 ];
__device__ __nv_bfloat16 g_wpbf[ 256 * 256 ];
__device__ float g_Fc[ 33 * 34 ];
__device__ float g_Fs[ 33 * 34 ];
__device__ float g_Ic[ 33 * 34 ];
__device__ float g_Is[ 33 * 34 ];

// ---------------------------------------------------------------------------
// Helpers
// ---------------------------------------------------------------------------
__device__ __forceinline__ uint32_t smem_u32(const void* p) {
    uint32_t a;
    asm("{ .reg .u64 t; cvta.to.shared.u64 t, %1; cvt.u32.u64 %0, t; }"
        : "=r"(a) : "l"(p));
    return a;
}

#define CP_ASYNC16(dst_u32, src_ptr) \
    asm volatile("cp.async.cg.shared.global [%0], [%1], 16;" \
        :: "r"(dst_u32), "l"(src_ptr))
#define CP_COMMIT() asm volatile("cp.async.commit_group;")
#define CP_WAIT1()  asm volatile("cp.async.wait_group 1;")
#define CP_WAIT0()  asm volatile("cp.async.wait_group 0;")

__device__ __forceinline__ void mma16n8k16bf(float* c, const uint32_t* a,
                                             const uint32_t* b) {
    asm volatile(
        "mma.sync.aligned.m16n8k16.row.col.f32.bf16.bf16.f32 "
        "{%0,%1,%2,%3}, {%4,%5,%6,%7}, {%8,%9}, {%0,%1,%2,%3};"
        : "+f"(c[0]), "+f"(c[1]), "+f"(c[2]), "+f"(c[3])
        : "r"(a[0]), "r"(a[1]), "r"(a[2]), "r"(a[3]), "r"(b[0]), "r"(b[1]));
}

__device__ __forceinline__ int win2pix(int t) {
    int b   = t >> 16;
    int rem = t & 65535;
    int wl  = rem >> 6;
    int n   = rem & 63;
    int wh  = wl >> 5, ww = wl & 31;
    int i   = n >> 3,  j  = n & 7;
    return (b * 256 + wh * 8 + i) * 256 + (ww * 8 + j);
}

__device__ __forceinline__ float dot4(float4 a, float4 b) {
    return a.x * b.x + a.y * b.y + a.z * b.z + a.w * b.w;
}

__device__ __forceinline__ void bf8_to_f8(uint4 r, float* o) {
    const __nv_bfloat162* p = (const __nv_bfloat162*)&r;
    #pragma unroll
    for (int i = 0; i < 4; i++) {
        float2 f = __bfloat1622float2(p[i]);
        o[2 * i] = f.x; o[2 * i + 1] = f.y;
    }
}

// ---------------------------------------------------------------------------
// DFT matrix init
// ---------------------------------------------------------------------------
__global__ void init_dft_kernel() {
    int i = blockIdx.x * blockDim.x + threadIdx.x;
    if (i < 33 * 34) {
        int r = i / 34, c = i % 34;
        float fc = 0.f, fs = 0.f, ic = 0.f, is = 0.f;
        if (c < 33) {
            float cs = cospif((float)(r * c) / 32.0f);
            float sn = sinpif((float)(r * c) / 32.0f);
            fc = 0.125f * cs;
            fs = -0.125f * sn;
            if (c == 0)       ic = 0.125f;
            else if (c == 32) ic = 0.125f * cospif((float)r);
            else              ic = 0.25f * cs;
            is = -0.25f * sn;
        }
        g_Fc[i] = fc; g_Fs[i] = fs; g_Ic[i] = ic; g_Is[i] = is;
    }
}

__global__ void conv_w_kernel(const float* __restrict__ w1,
                              const float* __restrict__ w2,
                              const float* __restrict__ wq,
                              const float* __restrict__ wp) {
    int i = blockIdx.x * blockDim.x + threadIdx.x;
    if (i < 1024 * 256) {
        g_w1bf[i] = __float2bfloat16_rn(w1[i]);
        g_w2bf[i] = __float2bfloat16_rn(w2[i]);
    }
    if (i < 768 * 256)  g_wqbf[i] = __float2bfloat16_rn(wq[i]);
    if (i < 256 * 256)  g_wpbf[i] = __float2bfloat16_rn(wp[i]);
}

// ---------------------------------------------------------------------------
// LayerNorm -> bf16, warp-per-row
// ---------------------------------------------------------------------------
__global__ __launch_bounds__(256)
void ln_bf16_kernel(const float* __restrict__ xin,
                    const float* __restrict__ w,
                    const float* __restrict__ b,
                    __nv_bfloat16* __restrict__ out, int winmap) {
    int warp = threadIdx.x >> 5, lane = threadIdx.x & 31;
    int t = blockIdx.x * 8 + warp;
    int rin = winmap ? win2pix(t) : t;
    const float4* src = (const float4*)(xin + (size_t)rin * CC) + lane * 2;
    float4 v0 = src[0], v1 = src[1];
    float s = v0.x + v0.y + v0.z + v0.w + v1.x + v1.y + v1.z + v1.w;
    float sq = v0.x * v0.x + v0.y * v0.y + v0.z * v0.z + v0.w * v0.w
             + v1.x * v1.x + v1.y * v1.y + v1.z * v1.z + v1.w * v1.w;
    #pragma unroll
    for (int o = 16; o; o >>= 1) {
        s  += __shfl_xor_sync(0xffffffffu, s,  o);
        sq += __shfl_xor_sync(0xffffffffu, sq, o);
    }
    float mean = s * (1.0f / CC);
    float var  = sq * (1.0f / CC) - mean * mean;
    float rstd = rsqrtf(var + 1e-5f);
    const float4* wp4 = (const float4*)w + lane * 2;
    const float4* bp4 = (const float4*)b + lane * 2;
    float4 w0 = wp4[0], w1 = wp4[1];
    float4 b0 = bp4[0], b1 = bp4[1];
    __nv_bfloat162 o4[4];
    o4[0] = __floats2bfloat162_rn((v0.x - mean) * rstd * w0.x + b0.x,
                                  (v0.y - mean) * rstd * w0.y + b0.y);
    o4[1] = __floats2bfloat162_rn((v0.z - mean) * rstd * w0.z + b0.z,
                                  (v0.w - mean) * rstd * w0.w + b0.w);
    o4[2] = __floats2bfloat162_rn((v1.x - mean) * rstd * w1.x + b1.x,
                                  (v1.y - mean) * rstd * w1.y + b1.y);
    o4[3] = __floats2bfloat162_rn((v1.z - mean) * rstd * w1.z + b1.z,
                                  (v1.w - mean) * rstd * w1.w + b1.w);
    *(uint4*)(out + (size_t)t * CC + lane * 8) = *(uint4*)o4;
}

// ---------------------------------------------------------------------------
// bf16 mma.sync GEMM, 512 threads / 16 warps, 128x256 tile, warp 64x32.
// EPI: 1 GELU->bf16; 2 +res fp32; 3 winrev+res fp32; 4 plain bf16
// ---------------------------------------------------------------------------
#define HPAD 72
#define A_STG_H (128 * HPAD)
#define B_STG_H (256 * HPAD)
#define BF_SMEM (3 * (A_STG_H + B_STG_H) * 2)

template<int EPI>
__global__ __launch_bounds__(512, 1)
void gemm_bf16(const __nv_bfloat16* __restrict__ A,
               const __nv_bfloat16* __restrict__ W,
               const float* __restrict__ bias, void* __restrict__ Cv,
               int M, int N, int K, const float* __restrict__ res) {
    extern __shared__ char smc[];
    __nv_bfloat16* AsBase = (__nv_bfloat16*)smc;
    __nv_bfloat16* BsBase = AsBase + 3 * A_STG_H;
    uint32_t sA = smem_u32(AsBase);
    uint32_t sB = smem_u32(BsBase);

    int tid = threadIdx.x;
    int m0 = blockIdx.y * 128, n0 = blockIdx.x * 256;
    int wid = tid >> 5, lane = tid & 31;
    int wm = (wid & 1) * 64, wn = (wid >> 1) * 32;
    int grp = lane >> 2, tg = lane & 3;

    float acc[4][4][4];
    #pragma unroll
    for (int a = 0; a < 4; a++)
        #pragma unroll
        for (int b = 0; b < 4; b++)
            #pragma unroll
            for (int c = 0; c < 4; c++) acc[a][b][c] = 0.f;

    const int NC = K / 64;

    #pragma unroll
    for (int pc = 0; pc < 2; pc++) {
        #pragma unroll
        for (int t = 0; t < 2; t++) {
            int idx = tid + t * 512;
            int row = idx >> 3, q = idx & 7;
            CP_ASYNC16(sA + (uint32_t)(pc * A_STG_H + row * HPAD + q * 8) * 2u,
                       A + (size_t)(m0 + row) * K + pc * 64 + q * 8);
        }
        #pragma unroll
        for (int t = 0; t < 4; t++) {
            int idx = tid + t * 512;
            int row = idx >> 3, q = idx & 7;
            CP_ASYNC16(sB + (uint32_t)(pc * B_STG_H + row * HPAD + q * 8) * 2u,
                       W + (size_t)(n0 + row) * K + pc * 64 + q * 8);
        }
        CP_COMMIT();
    }

    for (int i = 0; i < NC; i++) {
        if (i + 1 < NC) CP_WAIT1(); else CP_WAIT0();
        __syncthreads();
        if (i + 2 < NC) {
            int st = (i + 2) % 3;
            #pragma unroll
            for (int t = 0; t < 2; t++) {
                int idx = tid + t * 512;
                int row = idx >> 3, q = idx & 7;
                CP_ASYNC16(sA + (uint32_t)(st * A_STG_H + row * HPAD + q * 8) * 2u,
                           A + (size_t)(m0 + row) * K + (i + 2) * 64 + q * 8);
            }
            #pragma unroll
            for (int t = 0; t < 4; t++) {
                int idx = tid + t * 512;
                int row = idx >> 3, q = idx & 7;
                CP_ASYNC16(sB + (uint32_t)(st * B_STG_H + row * HPAD + q * 8) * 2u,
                           W + (size_t)(n0 + row) * K + (i + 2) * 64 + q * 8);
            }
            CP_COMMIT();
        }

        const __nv_bfloat16* As = AsBase + (i % 3) * A_STG_H;
        const __nv_bfloat16* Bs = BsBase + (i % 3) * B_STG_H;
        #pragma unroll
        for (int ks = 0; ks < 4; ks++) {
            uint32_t af[4][4];
            uint32_t bf[4][2];
            #pragma unroll
            for (int mi = 0; mi < 4; mi++) {
                int r = wm + mi * 16 + grp;
                af[mi][0] = *(const uint32_t*)(As + r * HPAD + ks * 16 + tg * 2);
                af[mi][1] = *(const uint32_t*)(As + (r + 8) * HPAD + ks * 16 + tg * 2);
                af[mi][2] = *(const uint32_t*)(As + r * HPAD + ks * 16 + tg * 2 + 8);
                af[mi][3] = *(const uint32_t*)(As + (r + 8) * HPAD + ks * 16 + tg * 2 + 8);
            }
            #pragma unroll
            for (int ni = 0; ni < 4; ni++) {
                int r = wn + ni * 8 + grp;
                bf[ni][0] = *(const uint32_t*)(Bs + r * HPAD + ks * 16 + tg * 2);
                bf[ni][1] = *(const uint32_t*)(Bs + r * HPAD + ks * 16 + tg * 2 + 8);
            }
            #pragma unroll
            for (int mi = 0; mi < 4; mi++)
                #pragma unroll
                for (int ni = 0; ni < 4; ni++)
                    mma16n8k16bf(acc[mi][ni], af[mi], bf[ni]);
        }
    }

    #pragma unroll
    for (int mi = 0; mi < 4; mi++) {
        #pragma unroll
        for (int half = 0; half < 2; half++) {
            int m = m0 + wm + mi * 16 + grp + half * 8;
            size_t orow = (EPI == 3) ? (size_t)win2pix(m) * N : (size_t)m * N;
            #pragma unroll
            for (int ni = 0; ni < 4; ni++) {
                int n = n0 + wn + ni * 8 + tg * 2;
                float vx = acc[mi][ni][half * 2 + 0] + bias[n];
                float vy = acc[mi][ni][half * 2 + 1] + bias[n + 1];
                if (EPI == 1) {
                    vx = 0.5f * vx * (1.0f + erff(vx * 0.7071067811865476f));
                    vy = 0.5f * vy * (1.0f + erff(vy * 0.7071067811865476f));
                    ((__nv_bfloat162*)Cv)[(orow + n) >> 1] = __floats2bfloat162_rn(vx, vy);
                } else if (EPI == 4) {
                    ((__nv_bfloat162*)Cv)[(orow + n) >> 1] = __floats2bfloat162_rn(vx, vy);
                } else {
                    vx += res[orow + n];
                    vy += res[orow + n + 1];
                    *(float2*)((float*)Cv + orow + n) = make_float2(vx, vy);
                }
            }
        }
    }
}

// ---------------------------------------------------------------------------
// Fused spectral qkv (bf16 in/out) with cos/sin symmetry
// ---------------------------------------------------------------------------
__global__ __launch_bounds__(256)
void spec_qkv_kernel(const __nv_bfloat16* __restrict__ qkvs,
                     const float* __restrict__ qkvb,
                     __nv_bfloat16* __restrict__ qkvf) {
    __shared__ float Fc[33 * 34];
    __shared__ float Fs[33 * 34];
    int w = blockIdx.x;
    int tid = threadIdx.x;
    int ch = blockIdx.y * 256 + tid;
    for (int m = tid; m < 33 * 34; m += 256) { Fc[m] = g_Fc[m]; Fs[m] = g_Fs[m]; }

    float e[33], o[32];
    const __nv_bfloat16* src = qkvs + (size_t)w * NTOK * 768 + ch;
    e[0]  = __bfloat162float(src[0]);
    e[32] = __bfloat162float(src[(size_t)32 * 768]);
    #pragma unroll
    for (int n = 1; n < 32; n++) {
        float a = __bfloat162float(src[(size_t)n * 768]);
        float b = __bfloat162float(src[(size_t)(64 - n) * 768]);
        e[n] = a + b;
        o[n] = a - b;
    }
    __syncthreads();

    float bb = qkvb[ch];
    __nv_bfloat16* dst = qkvf + (size_t)w * NF * 768 + ch;

    #pragma unroll 1
    for (int f = 0; f < 32; f += 2) {
        const float* R0 = Fc + f * 34;
        const float* R1 = R0 + 34;
        float s0 = 0.f, s0b = 0.f, s1 = 0.f, s1b = 0.f;
        #pragma unroll
        for (int n = 0; n < 32; n += 2) {
            s0  += R0[n] * e[n];     s0b += R0[n + 1] * e[n + 1];
            s1  += R1[n] * e[n];     s1b += R1[n + 1] * e[n + 1];
        }
        s0 += R0[32] * e[32];
        s1 += R1[32] * e[32];
        dst[(size_t)f * 768]       = __float2bfloat16_rn(s0 + s0b + ((f == 0) ? -7.0f * bb : bb));
        dst[(size_t)(f + 1) * 768] = __float2bfloat16_rn(s1 + s1b + bb);
    }
    {
        const float* R0 = Fc + 32 * 34;
        float s0 = 0.f, s0b = 0.f;
        #pragma unroll
        for (int n = 0; n < 32; n += 2) {
            s0 += R0[n] * e[n]; s0b += R0[n + 1] * e[n + 1];
        }
        s0 += R0[32] * e[32];
        dst[(size_t)32 * 768] = __float2bfloat16_rn(s0 + s0b + bb);
    }

    dst[(size_t)33 * 768] = __float2bfloat16_rn(bb);
    dst[(size_t)65 * 768] = __float2bfloat16_rn(bb);

    #pragma unroll 1
    for (int f = 1; f < 31; f += 2) {
        const float* R0 = Fs + f * 34;
        const float* R1 = R0 + 34;
        float s0 = 0.f, s0b = 0.f, s1 = 0.f, s1b = 0.f;
        #pragma unroll
        for (int n = 1; n < 31; n += 2) {
            s0  += R0[n] * o[n];     s0b += R0[n + 1] * o[n + 1];
            s1  += R1[n] * o[n];     s1b += R1[n + 1] * o[n + 1];
        }
        s0 += R0[31] * o[31];
        s1 += R1[31] * o[31];
        dst[(size_t)(33 + f) * 768] = __float2bfloat16_rn(s0 + s0b + bb);
        dst[(size_t)(34 + f) * 768] = __float2bfloat16_rn(s1 + s1b + bb);
    }
    {
        const float* R0 = Fs + 31 * 34;
        float s0 = 0.f, s0b = 0.f;
        #pragma unroll
        for (int n = 1; n < 31; n += 2) {
            s0 += R0[n] * o[n]; s0b += R0[n + 1] * o[n + 1];
        }
        s0 += R0[31] * o[31];
        dst[(size_t)64 * 768] = __float2bfloat16_rn(s0 + s0b + bb);
    }
}

// ---------------------------------------------------------------------------
// Inverse rfft: attnbf = bf16(attn(bf16) + irfft(outf))
// ---------------------------------------------------------------------------
__global__ __launch_bounds__(256)
void ifft_acc_kernel(const float* __restrict__ outf,
                     const __nv_bfloat16* __restrict__ attn,
                     __nv_bfloat16* __restrict__ attnbf) {
    __shared__ float Ic[33 * 34];
    __shared__ float Is[33 * 34];
    int w = blockIdx.x;
    int c = threadIdx.x;
    for (int m = c; m < 33 * 34; m += 256) { Ic[m] = g_Ic[m]; Is[m] = g_Is[m]; }

    float fr[NF];
    const float* src = outf + (size_t)w * NF * CC + c;
    #pragma unroll 11
    for (int r = 0; r < NF; r++) fr[r] = src[(size_t)r * CC];
    __syncthreads();

    const __nv_bfloat16* ain = attn + (size_t)w * NTOK * CC + c;
    __nv_bfloat16* dst = attnbf + (size_t)w * NTOK * CC + c;
    #pragma unroll 1
    for (int n = 0; n < 32; n += 2) {
        const float* C0 = Ic + n * 34;
        const float* C1 = C0 + 34;
        const float* S0 = Is + n * 34;
        const float* S1 = S0 + 34;
        float a0 = 0.f, a0b = 0.f, a1 = 0.f, a1b = 0.f;
        #pragma unroll
        for (int r = 0; r < 32; r += 2) {
            a0  += C0[r] * fr[r];     a0b += C0[r + 1] * fr[r + 1];
            a1  += C1[r] * fr[r];     a1b += C1[r + 1] * fr[r + 1];
        }
        a0 += C0[32] * fr[32];
        a1 += C1[32] * fr[32];
        float b0 = 0.f, b0b = 0.f, b1 = 0.f, b1b = 0.f;
        #pragma unroll
        for (int r = 1; r < 31; r += 2) {
            b0  += S0[r] * fr[33 + r];     b0b += S0[r + 1] * fr[34 + r];
            b1  += S1[r] * fr[33 + r];     b1b += S1[r + 1] * fr[34 + r];
        }
        b0 += S0[31] * fr[64];
        b1 += S1[31] * fr[64];
        float A0 = a0 + a0b, B0 = b0 + b0b;
        float A1 = a1 + a1b, B1 = b1 + b1b;
        dst[(size_t)n * CC] =
            __float2bfloat16_rn(__bfloat162float(ain[(size_t)n * CC]) + A0 + B0);
        if (n >= 1)
            dst[(size_t)(64 - n) * CC] =
                __float2bfloat16_rn(__bfloat162float(ain[(size_t)(64 - n) * CC]) + A0 - B0);
        dst[(size_t)(n + 1) * CC] =
            __float2bfloat16_rn(__bfloat162float(ain[(size_t)(n + 1) * CC]) + A1 + B1);
        dst[(size_t)(63 - n) * CC] =
            __float2bfloat16_rn(__bfloat162float(ain[(size_t)(63 - n) * CC]) + A1 - B1);
    }
    {
        const float* C0 = Ic + 32 * 34;
        float a0 = 0.f, a0b = 0.f;
        #pragma unroll
        for (int r = 0; r < 32; r += 2) {
            a0 += C0[r] * fr[r]; a0b += C0[r + 1] * fr[r + 1];
        }
        a0 += C0[32] * fr[32];
        dst[(size_t)32 * CC] =
            __float2bfloat16_rn(__bfloat162float(ain[(size_t)32 * CC]) + a0 + a0b);
    }
}

// ---------------------------------------------------------------------------
// Spatial window attention: 2 windows per block (128 thr), fp16 score buffer
// ---------------------------------------------------------------------------
__global__ __launch_bounds__(128)
void attn_kernel(const __nv_bfloat16* __restrict__ qkv,
                 const float* __restrict__ rpb,
                 __nv_bfloat16* __restrict__ outp) {
    const int NT = NTOK;
    __shared__ float ks[2][NT][36];
    __shared__ float vs[2][NT][36];
    __shared__ __half ss[2][NT][66];
    __shared__ float rpb_s[225];

    int w2 = blockIdx.x, h = blockIdx.y;
    int tid = threadIdx.x;
    int sub = tid >> 6;
    int row = tid & 63;
    int w = w2 * 2 + sub;

    float4 qv[8];
    {
        const uint4* base = (const uint4*)(qkv + ((size_t)w * NT + row) * 768 + h * 32);
        #pragma unroll
        for (int i = 0; i < 4; i++) {
            float qf[8];
            bf8_to_f8(base[i], qf);
            qv[2 * i]     = make_float4(qf[0] * SCALE, qf[1] * SCALE, qf[2] * SCALE, qf[3] * SCALE);
            qv[2 * i + 1] = make_float4(qf[4] * SCALE, qf[5] * SCALE, qf[6] * SCALE, qf[7] * SCALE);
            bf8_to_f8(base[32 + i], &ks[sub][row][i * 8]);
            bf8_to_f8(base[64 + i], &vs[sub][row][i * 8]);
        }
    }
    for (int m = tid; m < 225; m += 128) rpb_s[m] = rpb[m * HEADS + h];
    __syncthreads();

    int yi = row >> 3, xi = row & 7;
    float mx = -1e30f;
    for (int j = 0; j < NT; j += 4) {
        const float4* k0 = (const float4*)ks[sub][j + 0];
        const float4* k1 = (const float4*)ks[sub][j + 1];
        const float4* k2 = (const float4*)ks[sub][j + 2];
        const float4* k3 = (const float4*)ks[sub][j + 3];
        float s0 = 0.f, s1 = 0.f, s2 = 0.f, s3 = 0.f;
        #pragma unroll
        for (int d4 = 0; d4 < 8; d4++) {
            float4 q = qv[d4];
            s0 += dot4(q, k0[d4]);
            s1 += dot4(q, k1[d4]);
            s2 += dot4(q, k2[d4]);
            s3 += dot4(q, k3[d4]);
        }
        int bi = (yi + 7) * 15 + (xi + 7);
        s0 += rpb_s[bi - ((j + 0) >> 3) * 15 - ((j + 0) & 7)];
        s1 += rpb_s[bi - ((j + 1) >> 3) * 15 - ((j + 1) & 7)];
        s2 += rpb_s[bi - ((j + 2) >> 3) * 15 - ((j + 2) & 7)];
        s3 += rpb_s[bi - ((j + 3) >> 3) * 15 - ((j + 3) & 7)];
        *(__half2*)&ss[sub][row][j]     = __floats2half2_rn(s0, s1);
        *(__half2*)&ss[sub][row][j + 2] = __floats2half2_rn(s2, s3);
        mx = fmaxf(mx, fmaxf(fmaxf(s0, s1), fmaxf(s2, s3)));
    }

    float sum = 0.f;
    #pragma unroll 8
    for (int jj = 0; jj < NT; jj += 2) {
        float2 f = __half22float2(*(__half2*)&ss[sub][row][jj]);
        float e0 = __expf(f.x - mx);
        float e1 = __expf(f.y - mx);
        *(__half2*)&ss[sub][row][jj] = __floats2half2_rn(e0, e1);
        sum += e0 + e1;
    }
    float inv = 1.0f / sum;

    float4 av[8];
    #pragma unroll
    for (int d4 = 0; d4 < 8; d4++) av[d4] = make_float4(0.f, 0.f, 0.f, 0.f);
    for (int jj = 0; jj < NT; jj += 2) {
        float2 p = __half22float2(*(__half2*)&ss[sub][row][jj]);
        const float4* v0 = (const float4*)vs[sub][jj];
        const float4* v1 = (const float4*)vs[sub][jj + 1];
        #pragma unroll
        for (int d4 = 0; d4 < 8; d4++) {
            float4 a = av[d4];
            float4 x0 = v0[d4], x1 = v1[d4];
            a.x += p.x * x0.x + p.y * x1.x;
            a.y += p.x * x0.y + p.y * x1.y;
            a.z += p.x * x0.z + p.y * x1.z;
            a.w += p.x * x0.w + p.y * x1.w;
            av[d4] = a;
        }
    }

    __nv_bfloat162* ob = (__nv_bfloat162*)(outp + ((size_t)w * NT + row) * CC + h * 32);
    #pragma unroll
    for (int d4 = 0; d4 < 8; d4++) {
        float4 a = av[d4];
        ob[2 * d4]     = __floats2bfloat162_rn(a.x * inv, a.y * inv);
        ob[2 * d4 + 1] = __floats2bfloat162_rn(a.z * inv, a.w * inv);
    }
}

// ---------------------------------------------------------------------------
// Spectral attention: 2 windows per block, bf16 input, fp16 score buffer
// ---------------------------------------------------------------------------
__global__ __launch_bounds__(160)
void attn_spec2_kernel(const __nv_bfloat16* __restrict__ qkv,
                       float* __restrict__ outp) {
    __shared__ float ks[2][NF][36];
    __shared__ float vs[2][NF][36];
    __shared__ __half ss[2][NF][66];

    int w2 = blockIdx.x, h = blockIdx.y;
    int tid = threadIdx.x;
    int sub = tid / NF;
    int row = tid % NF;
    bool act = tid < 2 * NF;
    int w = w2 * 2 + sub;

    float4 qv[8];
    if (act) {
        const uint4* base = (const uint4*)(qkv + ((size_t)w * NF + row) * 768 + h * 32);
        #pragma unroll
        for (int i = 0; i < 4; i++) {
            float qf[8];
            bf8_to_f8(base[i], qf);
            qv[2 * i]     = make_float4(qf[0] * SCALE, qf[1] * SCALE, qf[2] * SCALE, qf[3] * SCALE);
            qv[2 * i + 1] = make_float4(qf[4] * SCALE, qf[5] * SCALE, qf[6] * SCALE, qf[7] * SCALE);
            bf8_to_f8(base[32 + i], &ks[sub][row][i * 8]);
            bf8_to_f8(base[64 + i], &vs[sub][row][i * 8]);
        }
    }
    __syncthreads();
    if (!act) return;

    float mx = -1e30f;
    int j = 0;
    for (; j + 3 < NF; j += 4) {
        const float4* k0 = (const float4*)ks[sub][j + 0];
        const float4* k1 = (const float4*)ks[sub][j + 1];
        const float4* k2 = (const float4*)ks[sub][j + 2];
        const float4* k3 = (const float4*)ks[sub][j + 3];
        float s0 = 0.f, s1 = 0.f, s2 = 0.f, s3 = 0.f;
        #pragma unroll
        for (int d4 = 0; d4 < 8; d4++) {
            float4 q = qv[d4];
            s0 += dot4(q, k0[d4]);
            s1 += dot4(q, k1[d4]);
            s2 += dot4(q, k2[d4]);
            s3 += dot4(q, k3[d4]);
        }
        *(__half2*)&ss[sub][row][j]     = __floats2half2_rn(s0, s1);
        *(__half2*)&ss[sub][row][j + 2] = __floats2half2_rn(s2, s3);
        mx = fmaxf(mx, fmaxf(fmaxf(s0, s1), fmaxf(s2, s3)));
    }
    {   // tail pair (64, 65)
        const float4* k0 = (const float4*)ks[sub][64];
        const float4* k1 = (const float4*)ks[sub][65];
        float s0 = 0.f, s1 = 0.f;
        #pragma unroll
        for (int d4 = 0; d4 < 8; d4++) {
            float4 q = qv[d4];
            s0 += dot4(q, k0[d4]);
            s1 += dot4(q, k1[d4]);
        }
        *(__half2*)&ss[sub][row][64] = __floats2half2_rn(s0, s1);
        mx = fmaxf(mx, fmaxf(s0, s1));
    }

    float sum = 0.f;
    #pragma unroll 11
    for (int jj = 0; jj < NF; jj += 2) {
        float2 f = __half22float2(*(__half2*)&ss[sub][row][jj]);
        float e0 = __expf(f.x - mx);
        float e1 = __expf(f.y - mx);
        *(__half2*)&ss[sub][row][jj] = __floats2half2_rn(e0, e1);
        sum += e0 + e1;
    }
    float inv = 1.0f / sum;

    float4 av[8];
    #pragma unroll
    for (int d4 = 0; d4 < 8; d4++) av[d4] = make_float4(0.f, 0.f, 0.f, 0.f);
    for (int jj = 0; jj < NF; jj += 2) {
        float2 p = __half22float2(*(__half2*)&ss[sub][row][jj]);
        const float4* v0 = (const float4*)vs[sub][jj];
        const float4* v1 = (const float4*)vs[sub][jj + 1];
        #pragma unroll
        for (int d4 = 0; d4 < 8; d4++) {
            float4 a = av[d4];
            float4 x0 = v0[d4], x1 = v1[d4];
            a.x += p.x * x0.x + p.y * x1.x;
            a.y += p.x * x0.y + p.y * x1.y;
            a.z += p.x * x0.z + p.y * x1.z;
            a.w += p.x * x0.w + p.y * x1.w;
            av[d4] = a;
        }
    }

    float4* ob = (float4*)(outp + ((size_t)w * NF + row) * CC + h * 32);
    #pragma unroll
    for (int d4 = 0; d4 < 8; d4++) {
        float4 a = av[d4];
        ob[d4] = make_float4(a.x * inv, a.y * inv, a.z * inv, a.w * inv);
    }
}

// ---------------------------------------------------------------------------
// Launch
// ---------------------------------------------------------------------------
extern "C" void kernel_launch(void* const* d_in, const int* in_sizes, int n_in,
                              void* d_out, int out_size) {
    (void)in_sizes; (void)n_in; (void)out_size;
    const float* x     = (const float*)d_in[0];
    const float* n1w   = (const float*)d_in[2];
    const float* n1b   = (const float*)d_in[3];
    const float* qkvw  = (const float*)d_in[4];
    const float* qkvb  = (const float*)d_in[5];
    const float* rpb   = (const float*)d_in[6];
    const float* projw = (const float*)d_in[7];
    const float* projb = (const float*)d_in[8];
    const float* n2w   = (const float*)d_in[9];
    const float* n2b   = (const float*)d_in[10];
    const float* fc1w  = (const float*)d_in[11];
    const float* fc1b  = (const float*)d_in[12];
    const float* fc2w  = (const float*)d_in[13];
    const float* fc2b  = (const float*)d_in[14];
    float* out = (float*)d_out;

    float *outf, *x2;
    __nv_bfloat16 *xlnbf, *qkvs, *qkvf, *attnh, *attnbf, *hln, *h1, *w1bf, *w2bf, *wqbf, *wpbf;
    cudaGetSymbolAddress((void**)&xlnbf,  g_xlnbf);
    cudaGetSymbolAddress((void**)&qkvs,   g_qkvs);
    cudaGetSymbolAddress((void**)&qkvf,   g_qkvf);
    cudaGetSymbolAddress((void**)&attnh,  g_attnh);
    cudaGetSymbolAddress((void**)&attnbf, g_attnbf);
    cudaGetSymbolAddress((void**)&outf,   g_outf);
    cudaGetSymbolAddress((void**)&x2,     g_x2);
    cudaGetSymbolAddress((void**)&hln,    g_hln);
    cudaGetSymbolAddress((void**)&h1,     g_h1);
    cudaGetSymbolAddress((void**)&w1bf,   g_w1bf);
    cudaGetSymbolAddress((void**)&w2bf,   g_w2bf);
    cudaGetSymbolAddress((void**)&wqbf,   g_wqbf);
    cudaGetSymbolAddress((void**)&wpbf,   g_wpbf);

    cudaFuncSetAttribute(gemm_bf16<1>, cudaFuncAttributeMaxDynamicSharedMemorySize, BF_SMEM);
    cudaFuncSetAttribute(gemm_bf16<2>, cudaFuncAttributeMaxDynamicSharedMemorySize, BF_SMEM);
    cudaFuncSetAttribute(gemm_bf16<3>, cudaFuncAttributeMaxDynamicSharedMemorySize, BF_SMEM);
    cudaFuncSetAttribute(gemm_bf16<4>, cudaFuncAttributeMaxDynamicSharedMemorySize, BF_SMEM);

    static cudaStream_t s1 = nullptr;
    static cudaEvent_t eF0 = nullptr, eJ0 = nullptr, eF1 = nullptr, eJ1 = nullptr;
    if (!s1) {
        cudaStreamCreateWithFlags(&s1, cudaStreamNonBlocking);
        cudaEventCreateWithFlags(&eF0, cudaEventDisableTiming);
        cudaEventCreateWithFlags(&eJ0, cudaEventDisableTiming);
        cudaEventCreateWithFlags(&eF1, cudaEventDisableTiming);
        cudaEventCreateWithFlags(&eJ1, cudaEventDisableTiming);
    }

    init_dft_kernel<<<5, 256>>>();

    // conv_w on side stream, overlapped with LN1
    cudaEventRecord(eF0, 0);
    cudaStreamWaitEvent(s1, eF0, 0);
    conv_w_kernel<<<1024, 256, 0, s1>>>(fc1w, fc2w, qkvw, projw);
    cudaEventRecord(eJ0, s1);

    // LN1 (+ window partition) -> bf16
    ln_bf16_kernel<<<TOKS / 8, 256>>>(x, n1w, n1b, xlnbf, 1);

    cudaStreamWaitEvent(0, eJ0, 0);

    // spatial qkv (bf16 in/out)
    gemm_bf16<4><<<dim3(768 / 256, TOKS / 128), 512, BF_SMEM>>>(
        xlnbf, wqbf, qkvb, qkvs, TOKS, 768, 256, nullptr);

    // fork: spatial attention on s1 || spectral chain on main
    cudaEventRecord(eF1, 0);
    cudaStreamWaitEvent(s1, eF1, 0);
    attn_kernel<<<dim3(NWIN / 2, HEADS), 128, 0, s1>>>(qkvs, rpb, attnh);

    spec_qkv_kernel<<<dim3(NWIN, 3), 256>>>(qkvs, qkvb, qkvf);
    attn_spec2_kernel<<<dim3(NWIN / 2, HEADS), 160>>>(qkvf, outf);

    cudaEventRecord(eJ1, s1);
    cudaStreamWaitEvent(0, eJ1, 0);

    // irfft + combine -> bf16 proj input
    ifft_acc_kernel<<<NWIN, 256>>>(outf, attnh, attnbf);

    // proj + window reverse + shortcut -> x2
    gemm_bf16<3><<<dim3(256 / 256, TOKS / 128), 512, BF_SMEM>>>(
        attnbf, wpbf, projb, x2, TOKS, 256, 256, x);

    // LN2 -> bf16
    ln_bf16_kernel<<<TOKS / 8, 256>>>(x2, n2w, n2b, hln, 0);

    // fc1 + GELU -> h1 (bf16)
    gemm_bf16<1><<<dim3(1024 / 256, TOKS / 128), 512, BF_SMEM>>>(
        hln, w1bf, fc1b, h1, TOKS, 1024, 256, nullptr);

    // fc2 + residual -> out
    gemm_bf16<2><<<dim3(256 / 256, TOKS / 128), 512, BF_SMEM>>>(
        h1, w2bf, fc2b, out, TOKS, 256, 1024, x2);
}

// round 17
// speedup vs baseline: 1.0452x; 1.0300x over previous
#include <cuda_runtime.h>
#include <cuda_bf16.h>
#include <cuda_fp16.h>
#include <math.h>
#include <stdint.h>

// ---------------------------------------------------------------------------
// Problem constants
// ---------------------------------------------------------------------------
#define CC      256
#define WS      8
#define NTOK    64
#define NF      66
#define HEADS   8
#define HD      32
#define NWIN    2048
#define TOKS    131072
#define SCALE   0.17677669529663687f

// ---------------------------------------------------------------------------
// Scratch
// ---------------------------------------------------------------------------
__device__ __nv_bfloat16 g_xlnbf[ (size_t)TOKS * CC ];
__device__ __nv_bfloat16 g_qkvs[ (size_t)NWIN * NTOK * 3 * CC ];
__device__ __nv_bfloat16 g_qkvf[ (size_t)NWIN * NF * 3 * CC ];
__device__ __nv_bfloat16 g_attnh[ (size_t)NWIN * NTOK * CC ];
__device__ __nv_bfloat16 g_attnbf[ (size_t)NWIN * NTOK * CC ];
__device__ __nv_bfloat16 g_outf[ (size_t)NWIN * NF * CC ];
__device__ float g_x2  [ (size_t)TOKS * CC ];
__device__ __nv_bfloat16 g_hln[ (size_t)TOKS * CC ];
__device__ __nv_bfloat16 g_h1 [ (size_t)TOKS * 4 * CC ];
__device__ __nv_bfloat16 g_w1bf[ 1024 * 256 ];
__device__ __nv_bfloat16 g_w2bf[ 256 * 1024 ];
__device__ __nv_bfloat16 g_wqbf[ 768 * 256 ];
__device__ __nv_bfloat16 g_wpbf[ 256 * 256 ];
__device__ float g_Fc[ 33 * 34 ];
__device__ float g_Fs[ 33 * 34 ];
__device__ float g_Ic[ 33 * 34 ];
__device__ float g_Is[ 33 * 34 ];

// ---------------------------------------------------------------------------
// Helpers
// ---------------------------------------------------------------------------
__device__ __forceinline__ uint32_t smem_u32(const void* p) {
    uint32_t a;
    asm("{ .reg .u64 t; cvta.to.shared.u64 t, %1; cvt.u32.u64 %0, t; }"
        : "=r"(a) : "l"(p));
    return a;
}

#define CP_ASYNC16(dst_u32, src_ptr) \
    asm volatile("cp.async.cg.shared.global [%0], [%1], 16;" \
        :: "r"(dst_u32), "l"(src_ptr))
#define CP_COMMIT() asm volatile("cp.async.commit_group;")
#define CP_WAIT1()  asm volatile("cp.async.wait_group 1;")
#define CP_WAIT0()  asm volatile("cp.async.wait_group 0;")

__device__ __forceinline__ void mma16n8k16bf(float* c, const uint32_t* a,
                                             const uint32_t* b) {
    asm volatile(
        "mma.sync.aligned.m16n8k16.row.col.f32.bf16.bf16.f32 "
        "{%0,%1,%2,%3}, {%4,%5,%6,%7}, {%8,%9}, {%0,%1,%2,%3};"
        : "+f"(c[0]), "+f"(c[1]), "+f"(c[2]), "+f"(c[3])
        : "r"(a[0]), "r"(a[1]), "r"(a[2]), "r"(a[3]), "r"(b[0]), "r"(b[1]));
}

__device__ __forceinline__ int win2pix(int t) {
    int b   = t >> 16;
    int rem = t & 65535;
    int wl  = rem >> 6;
    int n   = rem & 63;
    int wh  = wl >> 5, ww = wl & 31;
    int i   = n >> 3,  j  = n & 7;
    return (b * 256 + wh * 8 + i) * 256 + (ww * 8 + j);
}

__device__ __forceinline__ float dot4(float4 a, float4 b) {
    return a.x * b.x + a.y * b.y + a.z * b.z + a.w * b.w;
}

__device__ __forceinline__ void bf8_to_f8(uint4 r, float* o) {
    const __nv_bfloat162* p = (const __nv_bfloat162*)&r;
    #pragma unroll
    for (int i = 0; i < 4; i++) {
        float2 f = __bfloat1622float2(p[i]);
        o[2 * i] = f.x; o[2 * i + 1] = f.y;
    }
}

// ---------------------------------------------------------------------------
// DFT matrix init
// ---------------------------------------------------------------------------
__global__ void init_dft_kernel() {
    int i = blockIdx.x * blockDim.x + threadIdx.x;
    if (i < 33 * 34) {
        int r = i / 34, c = i % 34;
        float fc = 0.f, fs = 0.f, ic = 0.f, is = 0.f;
        if (c < 33) {
            float cs = cospif((float)(r * c) / 32.0f);
            float sn = sinpif((float)(r * c) / 32.0f);
            fc = 0.125f * cs;
            fs = -0.125f * sn;
            if (c == 0)       ic = 0.125f;
            else if (c == 32) ic = 0.125f * cospif((float)r);
            else              ic = 0.25f * cs;
            is = -0.25f * sn;
        }
        g_Fc[i] = fc; g_Fs[i] = fs; g_Ic[i] = ic; g_Is[i] = is;
    }
}

__global__ void conv_w_kernel(const float* __restrict__ w1,
                              const float* __restrict__ w2,
                              const float* __restrict__ wq,
                              const float* __restrict__ wp) {
    int i = blockIdx.x * blockDim.x + threadIdx.x;
    if (i < 1024 * 256) {
        g_w1bf[i] = __float2bfloat16_rn(w1[i]);
        g_w2bf[i] = __float2bfloat16_rn(w2[i]);
    }
    if (i < 768 * 256)  g_wqbf[i] = __float2bfloat16_rn(wq[i]);
    if (i < 256 * 256)  g_wpbf[i] = __float2bfloat16_rn(wp[i]);
}

// ---------------------------------------------------------------------------
// LayerNorm -> bf16, warp-per-row
// ---------------------------------------------------------------------------
__global__ __launch_bounds__(256)
void ln_bf16_kernel(const float* __restrict__ xin,
                    const float* __restrict__ w,
                    const float* __restrict__ b,
                    __nv_bfloat16* __restrict__ out, int winmap) {
    int warp = threadIdx.x >> 5, lane = threadIdx.x & 31;
    int t = blockIdx.x * 8 + warp;
    int rin = winmap ? win2pix(t) : t;
    const float4* src = (const float4*)(xin + (size_t)rin * CC) + lane * 2;
    float4 v0 = src[0], v1 = src[1];
    float s = v0.x + v0.y + v0.z + v0.w + v1.x + v1.y + v1.z + v1.w;
    float sq = v0.x * v0.x + v0.y * v0.y + v0.z * v0.z + v0.w * v0.w
             + v1.x * v1.x + v1.y * v1.y + v1.z * v1.z + v1.w * v1.w;
    #pragma unroll
    for (int o = 16; o; o >>= 1) {
        s  += __shfl_xor_sync(0xffffffffu, s,  o);
        sq += __shfl_xor_sync(0xffffffffu, sq, o);
    }
    float mean = s * (1.0f / CC);
    float var  = sq * (1.0f / CC) - mean * mean;
    float rstd = rsqrtf(var + 1e-5f);
    const float4* wp4 = (const float4*)w + lane * 2;
    const float4* bp4 = (const float4*)b + lane * 2;
    float4 w0 = wp4[0], w1 = wp4[1];
    float4 b0 = bp4[0], b1 = bp4[1];
    __nv_bfloat162 o4[4];
    o4[0] = __floats2bfloat162_rn((v0.x - mean) * rstd * w0.x + b0.x,
                                  (v0.y - mean) * rstd * w0.y + b0.y);
    o4[1] = __floats2bfloat162_rn((v0.z - mean) * rstd * w0.z + b0.z,
                                  (v0.w - mean) * rstd * w0.w + b0.w);
    o4[2] = __floats2bfloat162_rn((v1.x - mean) * rstd * w1.x + b1.x,
                                  (v1.y - mean) * rstd * w1.y + b1.y);
    o4[3] = __floats2bfloat162_rn((v1.z - mean) * rstd * w1.z + b1.z,
                                  (v1.w - mean) * rstd * w1.w + b1.w);
    *(uint4*)(out + (size_t)t * CC + lane * 8) = *(uint4*)o4;
}

// ---------------------------------------------------------------------------
// bf16 mma.sync GEMM: 256 threads / 8 warps, 128x128 CTA tile, warp 64x32.
// __launch_bounds__(256,2): 2 CTAs/SM (32K regs + 110.6KB smem each).
// EPI: 1 GELU->bf16; 2 +res fp32; 3 winrev+res fp32; 4 plain bf16
// ---------------------------------------------------------------------------
#define HPAD 72
#define A_STG_H (128 * HPAD)
#define B_STG_H (128 * HPAD)
#define BF_SMEM (3 * (A_STG_H + B_STG_H) * 2)

template<int EPI>
__global__ __launch_bounds__(256, 2)
void gemm_bf16(const __nv_bfloat16* __restrict__ A,
               const __nv_bfloat16* __restrict__ W,
               const float* __restrict__ bias, void* __restrict__ Cv,
               int M, int N, int K, const float* __restrict__ res) {
    extern __shared__ char smc[];
    __nv_bfloat16* AsBase = (__nv_bfloat16*)smc;
    __nv_bfloat16* BsBase = AsBase + 3 * A_STG_H;
    uint32_t sA = smem_u32(AsBase);
    uint32_t sB = smem_u32(BsBase);

    int tid = threadIdx.x;
    int m0 = blockIdx.y * 128, n0 = blockIdx.x * 128;
    int wid = tid >> 5, lane = tid & 31;
    int wm = (wid & 1) * 64, wn = (wid >> 1) * 32;
    int grp = lane >> 2, tg = lane & 3;

    float acc[4][4][4];
    #pragma unroll
    for (int a = 0; a < 4; a++)
        #pragma unroll
        for (int b = 0; b < 4; b++)
            #pragma unroll
            for (int c = 0; c < 4; c++) acc[a][b][c] = 0.f;

    const int NC = K / 64;

    #pragma unroll
    for (int pc = 0; pc < 2; pc++) {
        #pragma unroll
        for (int t = 0; t < 4; t++) {
            int idx = tid + t * 256;
            int row = idx >> 3, q = idx & 7;
            CP_ASYNC16(sA + (uint32_t)(pc * A_STG_H + row * HPAD + q * 8) * 2u,
                       A + (size_t)(m0 + row) * K + pc * 64 + q * 8);
        }
        #pragma unroll
        for (int t = 0; t < 4; t++) {
            int idx = tid + t * 256;
            int row = idx >> 3, q = idx & 7;
            CP_ASYNC16(sB + (uint32_t)(pc * B_STG_H + row * HPAD + q * 8) * 2u,
                       W + (size_t)(n0 + row) * K + pc * 64 + q * 8);
        }
        CP_COMMIT();
    }

    for (int i = 0; i < NC; i++) {
        if (i + 1 < NC) CP_WAIT1(); else CP_WAIT0();
        __syncthreads();
        if (i + 2 < NC) {
            int st = (i + 2) % 3;
            #pragma unroll
            for (int t = 0; t < 4; t++) {
                int idx = tid + t * 256;
                int row = idx >> 3, q = idx & 7;
                CP_ASYNC16(sA + (uint32_t)(st * A_STG_H + row * HPAD + q * 8) * 2u,
                           A + (size_t)(m0 + row) * K + (i + 2) * 64 + q * 8);
            }
            #pragma unroll
            for (int t = 0; t < 4; t++) {
                int idx = tid + t * 256;
                int row = idx >> 3, q = idx & 7;
                CP_ASYNC16(sB + (uint32_t)(st * B_STG_H + row * HPAD + q * 8) * 2u,
                           W + (size_t)(n0 + row) * K + (i + 2) * 64 + q * 8);
            }
            CP_COMMIT();
        }

        const __nv_bfloat16* As = AsBase + (i % 3) * A_STG_H;
        const __nv_bfloat16* Bs = BsBase + (i % 3) * B_STG_H;
        #pragma unroll
        for (int ks = 0; ks < 4; ks++) {
            uint32_t af[4][4];
            uint32_t bf[4][2];
            #pragma unroll
            for (int mi = 0; mi < 4; mi++) {
                int r = wm + mi * 16 + grp;
                af[mi][0] = *(const uint32_t*)(As + r * HPAD + ks * 16 + tg * 2);
                af[mi][1] = *(const uint32_t*)(As + (r + 8) * HPAD + ks * 16 + tg * 2);
                af[mi][2] = *(const uint32_t*)(As + r * HPAD + ks * 16 + tg * 2 + 8);
                af[mi][3] = *(const uint32_t*)(As + (r + 8) * HPAD + ks * 16 + tg * 2 + 8);
            }
            #pragma unroll
            for (int ni = 0; ni < 4; ni++) {
                int r = wn + ni * 8 + grp;
                bf[ni][0] = *(const uint32_t*)(Bs + r * HPAD + ks * 16 + tg * 2);
                bf[ni][1] = *(const uint32_t*)(Bs + r * HPAD + ks * 16 + tg * 2 + 8);
            }
            #pragma unroll
            for (int mi = 0; mi < 4; mi++)
                #pragma unroll
                for (int ni = 0; ni < 4; ni++)
                    mma16n8k16bf(acc[mi][ni], af[mi], bf[ni]);
        }
    }

    #pragma unroll
    for (int mi = 0; mi < 4; mi++) {
        #pragma unroll
        for (int half = 0; half < 2; half++) {
            int m = m0 + wm + mi * 16 + grp + half * 8;
            size_t orow = (EPI == 3) ? (size_t)win2pix(m) * N : (size_t)m * N;
            #pragma unroll
            for (int ni = 0; ni < 4; ni++) {
                int n = n0 + wn + ni * 8 + tg * 2;
                float vx = acc[mi][ni][half * 2 + 0] + bias[n];
                float vy = acc[mi][ni][half * 2 + 1] + bias[n + 1];
                if (EPI == 1) {
                    vx = 0.5f * vx * (1.0f + erff(vx * 0.7071067811865476f));
                    vy = 0.5f * vy * (1.0f + erff(vy * 0.7071067811865476f));
                    ((__nv_bfloat162*)Cv)[(orow + n) >> 1] = __floats2bfloat162_rn(vx, vy);
                } else if (EPI == 4) {
                    ((__nv_bfloat162*)Cv)[(orow + n) >> 1] = __floats2bfloat162_rn(vx, vy);
                } else {
                    vx += res[orow + n];
                    vy += res[orow + n + 1];
                    *(float2*)((float*)Cv + orow + n) = make_float2(vx, vy);
                }
            }
        }
    }
}

// ---------------------------------------------------------------------------
// Fused spectral qkv (bf16 in/out) with cos/sin symmetry
// ---------------------------------------------------------------------------
__global__ __launch_bounds__(256)
void spec_qkv_kernel(const __nv_bfloat16* __restrict__ qkvs,
                     const float* __restrict__ qkvb,
                     __nv_bfloat16* __restrict__ qkvf) {
    __shared__ float Fc[33 * 34];
    __shared__ float Fs[33 * 34];
    int w = blockIdx.x;
    int tid = threadIdx.x;
    int ch = blockIdx.y * 256 + tid;
    for (int m = tid; m < 33 * 34; m += 256) { Fc[m] = g_Fc[m]; Fs[m] = g_Fs[m]; }

    float e[33], o[32];
    const __nv_bfloat16* src = qkvs + (size_t)w * NTOK * 768 + ch;
    e[0]  = __bfloat162float(src[0]);
    e[32] = __bfloat162float(src[(size_t)32 * 768]);
    #pragma unroll
    for (int n = 1; n < 32; n++) {
        float a = __bfloat162float(src[(size_t)n * 768]);
        float b = __bfloat162float(src[(size_t)(64 - n) * 768]);
        e[n] = a + b;
        o[n] = a - b;
    }
    __syncthreads();

    float bb = qkvb[ch];
    __nv_bfloat16* dst = qkvf + (size_t)w * NF * 768 + ch;

    #pragma unroll 1
    for (int f = 0; f < 32; f += 2) {
        const float* R0 = Fc + f * 34;
        const float* R1 = R0 + 34;
        float s0 = 0.f, s0b = 0.f, s1 = 0.f, s1b = 0.f;
        #pragma unroll
        for (int n = 0; n < 32; n += 2) {
            s0  += R0[n] * e[n];     s0b += R0[n + 1] * e[n + 1];
            s1  += R1[n] * e[n];     s1b += R1[n + 1] * e[n + 1];
        }
        s0 += R0[32] * e[32];
        s1 += R1[32] * e[32];
        dst[(size_t)f * 768]       = __float2bfloat16_rn(s0 + s0b + ((f == 0) ? -7.0f * bb : bb));
        dst[(size_t)(f + 1) * 768] = __float2bfloat16_rn(s1 + s1b + bb);
    }
    {
        const float* R0 = Fc + 32 * 34;
        float s0 = 0.f, s0b = 0.f;
        #pragma unroll
        for (int n = 0; n < 32; n += 2) {
            s0 += R0[n] * e[n]; s0b += R0[n + 1] * e[n + 1];
        }
        s0 += R0[32] * e[32];
        dst[(size_t)32 * 768] = __float2bfloat16_rn(s0 + s0b + bb);
    }

    dst[(size_t)33 * 768] = __float2bfloat16_rn(bb);
    dst[(size_t)65 * 768] = __float2bfloat16_rn(bb);

    #pragma unroll 1
    for (int f = 1; f < 31; f += 2) {
        const float* R0 = Fs + f * 34;
        const float* R1 = R0 + 34;
        float s0 = 0.f, s0b = 0.f, s1 = 0.f, s1b = 0.f;
        #pragma unroll
        for (int n = 1; n < 31; n += 2) {
            s0  += R0[n] * o[n];     s0b += R0[n + 1] * o[n + 1];
            s1  += R1[n] * o[n];     s1b += R1[n + 1] * o[n + 1];
        }
        s0 += R0[31] * o[31];
        s1 += R1[31] * o[31];
        dst[(size_t)(33 + f) * 768] = __float2bfloat16_rn(s0 + s0b + bb);
        dst[(size_t)(34 + f) * 768] = __float2bfloat16_rn(s1 + s1b + bb);
    }
    {
        const float* R0 = Fs + 31 * 34;
        float s0 = 0.f, s0b = 0.f;
        #pragma unroll
        for (int n = 1; n < 31; n += 2) {
            s0 += R0[n] * o[n]; s0b += R0[n + 1] * o[n + 1];
        }
        s0 += R0[31] * o[31];
        dst[(size_t)64 * 768] = __float2bfloat16_rn(s0 + s0b + bb);
    }
}

// ---------------------------------------------------------------------------
// Inverse rfft: attnbf = bf16(attn(bf16) + irfft(outf bf16))
// ---------------------------------------------------------------------------
__global__ __launch_bounds__(256)
void ifft_acc_kernel(const __nv_bfloat16* __restrict__ outf,
                     const __nv_bfloat16* __restrict__ attn,
                     __nv_bfloat16* __restrict__ attnbf) {
    __shared__ float Ic[33 * 34];
    __shared__ float Is[33 * 34];
    int w = blockIdx.x;
    int c = threadIdx.x;
    for (int m = c; m < 33 * 34; m += 256) { Ic[m] = g_Ic[m]; Is[m] = g_Is[m]; }

    float fr[NF];
    const __nv_bfloat16* src = outf + (size_t)w * NF * CC + c;
    #pragma unroll 11
    for (int r = 0; r < NF; r++) fr[r] = __bfloat162float(src[(size_t)r * CC]);
    __syncthreads();

    const __nv_bfloat16* ain = attn + (size_t)w * NTOK * CC + c;
    __nv_bfloat16* dst = attnbf + (size_t)w * NTOK * CC + c;
    #pragma unroll 1
    for (int n = 0; n < 32; n += 2) {
        const float* C0 = Ic + n * 34;
        const float* C1 = C0 + 34;
        const float* S0 = Is + n * 34;
        const float* S1 = S0 + 34;
        float a0 = 0.f, a0b = 0.f, a1 = 0.f, a1b = 0.f;
        #pragma unroll
        for (int r = 0; r < 32; r += 2) {
            a0  += C0[r] * fr[r];     a0b += C0[r + 1] * fr[r + 1];
            a1  += C1[r] * fr[r];     a1b += C1[r + 1] * fr[r + 1];
        }
        a0 += C0[32] * fr[32];
        a1 += C1[32] * fr[32];
        float b0 = 0.f, b0b = 0.f, b1 = 0.f, b1b = 0.f;
        #pragma unroll
        for (int r = 1; r < 31; r += 2) {
            b0  += S0[r] * fr[33 + r];     b0b += S0[r + 1] * fr[34 + r];
            b1  += S1[r] * fr[33 + r];     b1b += S1[r + 1] * fr[34 + r];
        }
        b0 += S0[31] * fr[64];
        b1 += S1[31] * fr[64];
        float A0 = a0 + a0b, B0 = b0 + b0b;
        float A1 = a1 + a1b, B1 = b1 + b1b;
        dst[(size_t)n * CC] =
            __float2bfloat16_rn(__bfloat162float(ain[(size_t)n * CC]) + A0 + B0);
        if (n >= 1)
            dst[(size_t)(64 - n) * CC] =
                __float2bfloat16_rn(__bfloat162float(ain[(size_t)(64 - n) * CC]) + A0 - B0);
        dst[(size_t)(n + 1) * CC] =
            __float2bfloat16_rn(__bfloat162float(ain[(size_t)(n + 1) * CC]) + A1 + B1);
        dst[(size_t)(63 - n) * CC] =
            __float2bfloat16_rn(__bfloat162float(ain[(size_t)(63 - n) * CC]) + A1 - B1);
    }
    {
        const float* C0 = Ic + 32 * 34;
        float a0 = 0.f, a0b = 0.f;
        #pragma unroll
        for (int r = 0; r < 32; r += 2) {
            a0 += C0[r] * fr[r]; a0b += C0[r + 1] * fr[r + 1];
        }
        a0 += C0[32] * fr[32];
        dst[(size_t)32 * CC] =
            __float2bfloat16_rn(__bfloat162float(ain[(size_t)32 * CC]) + a0 + a0b);
    }
}

// ---------------------------------------------------------------------------
// Spatial window attention: 2 windows per block (128 thr), fp16 score buffer
// ---------------------------------------------------------------------------
__global__ __launch_bounds__(128)
void attn_kernel(const __nv_bfloat16* __restrict__ qkv,
                 const float* __restrict__ rpb,
                 __nv_bfloat16* __restrict__ outp) {
    const int NT = NTOK;
    __shared__ float ks[2][NT][36];
    __shared__ float vs[2][NT][36];
    __shared__ __half ss[2][NT][66];
    __shared__ float rpb_s[225];

    int w2 = blockIdx.x, h = blockIdx.y;
    int tid = threadIdx.x;
    int sub = tid >> 6;
    int row = tid & 63;
    int w = w2 * 2 + sub;

    float4 qv[8];
    {
        const uint4* base = (const uint4*)(qkv + ((size_t)w * NT + row) * 768 + h * 32);
        #pragma unroll
        for (int i = 0; i < 4; i++) {
            float qf[8];
            bf8_to_f8(base[i], qf);
            qv[2 * i]     = make_float4(qf[0] * SCALE, qf[1] * SCALE, qf[2] * SCALE, qf[3] * SCALE);
            qv[2 * i + 1] = make_float4(qf[4] * SCALE, qf[5] * SCALE, qf[6] * SCALE, qf[7] * SCALE);
            bf8_to_f8(base[32 + i], &ks[sub][row][i * 8]);
            bf8_to_f8(base[64 + i], &vs[sub][row][i * 8]);
        }
    }
    for (int m = tid; m < 225; m += 128) rpb_s[m] = rpb[m * HEADS + h];
    __syncthreads();

    int yi = row >> 3, xi = row & 7;
    float mx = -1e30f;
    for (int j = 0; j < NT; j += 4) {
        const float4* k0 = (const float4*)ks[sub][j + 0];
        const float4* k1 = (const float4*)ks[sub][j + 1];
        const float4* k2 = (const float4*)ks[sub][j + 2];
        const float4* k3 = (const float4*)ks[sub][j + 3];
        float s0 = 0.f, s1 = 0.f, s2 = 0.f, s3 = 0.f;
        #pragma unroll
        for (int d4 = 0; d4 < 8; d4++) {
            float4 q = qv[d4];
            s0 += dot4(q, k0[d4]);
            s1 += dot4(q, k1[d4]);
            s2 += dot4(q, k2[d4]);
            s3 += dot4(q, k3[d4]);
        }
        int bi = (yi + 7) * 15 + (xi + 7);
        s0 += rpb_s[bi - ((j + 0) >> 3) * 15 - ((j + 0) & 7)];
        s1 += rpb_s[bi - ((j + 1) >> 3) * 15 - ((j + 1) & 7)];
        s2 += rpb_s[bi - ((j + 2) >> 3) * 15 - ((j + 2) & 7)];
        s3 += rpb_s[bi - ((j + 3) >> 3) * 15 - ((j + 3) & 7)];
        *(__half2*)&ss[sub][row][j]     = __floats2half2_rn(s0, s1);
        *(__half2*)&ss[sub][row][j + 2] = __floats2half2_rn(s2, s3);
        mx = fmaxf(mx, fmaxf(fmaxf(s0, s1), fmaxf(s2, s3)));
    }

    float sum = 0.f;
    #pragma unroll 8
    for (int jj = 0; jj < NT; jj += 2) {
        float2 f = __half22float2(*(__half2*)&ss[sub][row][jj]);
        float e0 = __expf(f.x - mx);
        float e1 = __expf(f.y - mx);
        *(__half2*)&ss[sub][row][jj] = __floats2half2_rn(e0, e1);
        sum += e0 + e1;
    }
    float inv = 1.0f / sum;

    float4 av[8];
    #pragma unroll
    for (int d4 = 0; d4 < 8; d4++) av[d4] = make_float4(0.f, 0.f, 0.f, 0.f);
    for (int jj = 0; jj < NT; jj += 2) {
        float2 p = __half22float2(*(__half2*)&ss[sub][row][jj]);
        const float4* v0 = (const float4*)vs[sub][jj];
        const float4* v1 = (const float4*)vs[sub][jj + 1];
        #pragma unroll
        for (int d4 = 0; d4 < 8; d4++) {
            float4 a = av[d4];
            float4 x0 = v0[d4], x1 = v1[d4];
            a.x += p.x * x0.x + p.y * x1.x;
            a.y += p.x * x0.y + p.y * x1.y;
            a.z += p.x * x0.z + p.y * x1.z;
            a.w += p.x * x0.w + p.y * x1.w;
            av[d4] = a;
        }
    }

    __nv_bfloat162* ob = (__nv_bfloat162*)(outp + ((size_t)w * NT + row) * CC + h * 32);
    #pragma unroll
    for (int d4 = 0; d4 < 8; d4++) {
        float4 a = av[d4];
        ob[2 * d4]     = __floats2bfloat162_rn(a.x * inv, a.y * inv);
        ob[2 * d4 + 1] = __floats2bfloat162_rn(a.z * inv, a.w * inv);
    }
}

// ---------------------------------------------------------------------------
// Spectral attention: 2 windows per block, bf16 in/out, fp16 score buffer
// ---------------------------------------------------------------------------
__global__ __launch_bounds__(160)
void attn_spec2_kernel(const __nv_bfloat16* __restrict__ qkv,
                       __nv_bfloat16* __restrict__ outp) {
    __shared__ float ks[2][NF][36];
    __shared__ float vs[2][NF][36];
    __shared__ __half ss[2][NF][66];

    int w2 = blockIdx.x, h = blockIdx.y;
    int tid = threadIdx.x;
    int sub = tid / NF;
    int row = tid % NF;
    bool act = tid < 2 * NF;
    int w = w2 * 2 + sub;

    float4 qv[8];
    if (act) {
        const uint4* base = (const uint4*)(qkv + ((size_t)w * NF + row) * 768 + h * 32);
        #pragma unroll
        for (int i = 0; i < 4; i++) {
            float qf[8];
            bf8_to_f8(base[i], qf);
            qv[2 * i]     = make_float4(qf[0] * SCALE, qf[1] * SCALE, qf[2] * SCALE, qf[3] * SCALE);
            qv[2 * i + 1] = make_float4(qf[4] * SCALE, qf[5] * SCALE, qf[6] * SCALE, qf[7] * SCALE);
            bf8_to_f8(base[32 + i], &ks[sub][row][i * 8]);
            bf8_to_f8(base[64 + i], &vs[sub][row][i * 8]);
        }
    }
    __syncthreads();
    if (!act) return;

    float mx = -1e30f;
    int j = 0;
    for (; j + 3 < NF; j += 4) {
        const float4* k0 = (const float4*)ks[sub][j + 0];
        const float4* k1 = (const float4*)ks[sub][j + 1];
        const float4* k2 = (const float4*)ks[sub][j + 2];
        const float4* k3 = (const float4*)ks[sub][j + 3];
        float s0 = 0.f, s1 = 0.f, s2 = 0.f, s3 = 0.f;
        #pragma unroll
        for (int d4 = 0; d4 < 8; d4++) {
            float4 q = qv[d4];
            s0 += dot4(q, k0[d4]);
            s1 += dot4(q, k1[d4]);
            s2 += dot4(q, k2[d4]);
            s3 += dot4(q, k3[d4]);
        }
        *(__half2*)&ss[sub][row][j]     = __floats2half2_rn(s0, s1);
        *(__half2*)&ss[sub][row][j + 2] = __floats2half2_rn(s2, s3);
        mx = fmaxf(mx, fmaxf(fmaxf(s0, s1), fmaxf(s2, s3)));
    }
    {   // tail pair (64, 65)
        const float4* k0 = (const float4*)ks[sub][64];
        const float4* k1 = (const float4*)ks[sub][65];
        float s0 = 0.f, s1 = 0.f;
        #pragma unroll
        for (int d4 = 0; d4 < 8; d4++) {
            float4 q = qv[d4];
            s0 += dot4(q, k0[d4]);
            s1 += dot4(q, k1[d4]);
        }
        *(__half2*)&ss[sub][row][64] = __floats2half2_rn(s0, s1);
        mx = fmaxf(mx, fmaxf(s0, s1));
    }

    float sum = 0.f;
    #pragma unroll 11
    for (int jj = 0; jj < NF; jj += 2) {
        float2 f = __half22float2(*(__half2*)&ss[sub][row][jj]);
        float e0 = __expf(f.x - mx);
        float e1 = __expf(f.y - mx);
        *(__half2*)&ss[sub][row][jj] = __floats2half2_rn(e0, e1);
        sum += e0 + e1;
    }
    float inv = 1.0f / sum;

    float4 av[8];
    #pragma unroll
    for (int d4 = 0; d4 < 8; d4++) av[d4] = make_float4(0.f, 0.f, 0.f, 0.f);
    for (int jj = 0; jj < NF; jj += 2) {
        float2 p = __half22float2(*(__half2*)&ss[sub][row][jj]);
        const float4* v0 = (const float4*)vs[sub][jj];
        const float4* v1 = (const float4*)vs[sub][jj + 1];
        #pragma unroll
        for (int d4 = 0; d4 < 8; d4++) {
            float4 a = av[d4];
            float4 x0 = v0[d4], x1 = v1[d4];
            a.x += p.x * x0.x + p.y * x1.x;
            a.y += p.x * x0.y + p.y * x1.y;
            a.z += p.x * x0.z + p.y * x1.z;
            a.w += p.x * x0.w + p.y * x1.w;
            av[d4] = a;
        }
    }

    __nv_bfloat162* ob = (__nv_bfloat162*)(outp + ((size_t)w * NF + row) * CC + h * 32);
    #pragma unroll
    for (int d4 = 0; d4 < 8; d4++) {
        float4 a = av[d4];
        ob[2 * d4]     = __floats2bfloat162_rn(a.x * inv, a.y * inv);
        ob[2 * d4 + 1] = __floats2bfloat162_rn(a.z * inv, a.w * inv);
    }
}

// ---------------------------------------------------------------------------
// Launch
// ---------------------------------------------------------------------------
extern "C" void kernel_launch(void* const* d_in, const int* in_sizes, int n_in,
                              void* d_out, int out_size) {
    (void)in_sizes; (void)n_in; (void)out_size;
    const float* x     = (const float*)d_in[0];
    const float* n1w   = (const float*)d_in[2];
    const float* n1b   = (const float*)d_in[3];
    const float* qkvw  = (const float*)d_in[4];
    const float* qkvb  = (const float*)d_in[5];
    const float* rpb   = (const float*)d_in[6];
    const float* projw = (const float*)d_in[7];
    const float* projb = (const float*)d_in[8];
    const float* n2w   = (const float*)d_in[9];
    const float* n2b   = (const float*)d_in[10];
    const float* fc1w  = (const float*)d_in[11];
    const float* fc1b  = (const float*)d_in[12];
    const float* fc2w  = (const float*)d_in[13];
    const float* fc2b  = (const float*)d_in[14];
    float* out = (float*)d_out;

    float *x2;
    __nv_bfloat16 *xlnbf, *qkvs, *qkvf, *attnh, *attnbf, *outf, *hln, *h1,
                  *w1bf, *w2bf, *wqbf, *wpbf;
    cudaGetSymbolAddress((void**)&xlnbf,  g_xlnbf);
    cudaGetSymbolAddress((void**)&qkvs,   g_qkvs);
    cudaGetSymbolAddress((void**)&qkvf,   g_qkvf);
    cudaGetSymbolAddress((void**)&attnh,  g_attnh);
    cudaGetSymbolAddress((void**)&attnbf, g_attnbf);
    cudaGetSymbolAddress((void**)&outf,   g_outf);
    cudaGetSymbolAddress((void**)&x2,     g_x2);
    cudaGetSymbolAddress((void**)&hln,    g_hln);
    cudaGetSymbolAddress((void**)&h1,     g_h1);
    cudaGetSymbolAddress((void**)&w1bf,   g_w1bf);
    cudaGetSymbolAddress((void**)&w2bf,   g_w2bf);
    cudaGetSymbolAddress((void**)&wqbf,   g_wqbf);
    cudaGetSymbolAddress((void**)&wpbf,   g_wpbf);

    cudaFuncSetAttribute(gemm_bf16<1>, cudaFuncAttributeMaxDynamicSharedMemorySize, BF_SMEM);
    cudaFuncSetAttribute(gemm_bf16<2>, cudaFuncAttributeMaxDynamicSharedMemorySize, BF_SMEM);
    cudaFuncSetAttribute(gemm_bf16<3>, cudaFuncAttributeMaxDynamicSharedMemorySize, BF_SMEM);
    cudaFuncSetAttribute(gemm_bf16<4>, cudaFuncAttributeMaxDynamicSharedMemorySize, BF_SMEM);

    static cudaStream_t s1 = nullptr;
    static cudaEvent_t eF0 = nullptr, eJ0 = nullptr, eF1 = nullptr, eJ1 = nullptr;
    if (!s1) {
        cudaStreamCreateWithFlags(&s1, cudaStreamNonBlocking);
        cudaEventCreateWithFlags(&eF0, cudaEventDisableTiming);
        cudaEventCreateWithFlags(&eJ0, cudaEventDisableTiming);
        cudaEventCreateWithFlags(&eF1, cudaEventDisableTiming);
        cudaEventCreateWithFlags(&eJ1, cudaEventDisableTiming);
    }

    init_dft_kernel<<<5, 256>>>();

    // conv_w on side stream, overlapped with LN1
    cudaEventRecord(eF0, 0);
    cudaStreamWaitEvent(s1, eF0, 0);
    conv_w_kernel<<<1024, 256, 0, s1>>>(fc1w, fc2w, qkvw, projw);
    cudaEventRecord(eJ0, s1);

    // LN1 (+ window partition) -> bf16
    ln_bf16_kernel<<<TOKS / 8, 256>>>(x, n1w, n1b, xlnbf, 1);

    cudaStreamWaitEvent(0, eJ0, 0);

    // spatial qkv (bf16 in/out)
    gemm_bf16<4><<<dim3(768 / 128, TOKS / 128), 256, BF_SMEM>>>(
        xlnbf, wqbf, qkvb, qkvs, TOKS, 768, 256, nullptr);

    // fork: spatial attention on s1 || spectral chain on main
    cudaEventRecord(eF1, 0);
    cudaStreamWaitEvent(s1, eF1, 0);
    attn_kernel<<<dim3(NWIN / 2, HEADS), 128, 0, s1>>>(qkvs, rpb, attnh);

    spec_qkv_kernel<<<dim3(NWIN, 3), 256>>>(qkvs, qkvb, qkvf);
    attn_spec2_kernel<<<dim3(NWIN / 2, HEADS), 160>>>(qkvf, outf);

    cudaEventRecord(eJ1, s1);
    cudaStreamWaitEvent(0, eJ1, 0);

    // irfft + combine -> bf16 proj input
    ifft_acc_kernel<<<NWIN, 256>>>(outf, attnh, attnbf);

    // proj + window reverse + shortcut -> x2
    gemm_bf16<3><<<dim3(256 / 128, TOKS / 128), 256, BF_SMEM>>>(
        attnbf, wpbf, projb, x2, TOKS, 256, 256, x);

    // LN2 -> bf16
    ln_bf16_kernel<<<TOKS / 8, 256>>>(x2, n2w, n2b, hln, 0);

    // fc1 + GELU -> h1 (bf16)
    gemm_bf16<1><<<dim3(1024 / 128, TOKS / 128), 256, BF_SMEM>>>(
        hln, w1bf, fc1b, h1, TOKS, 1024, 256, nullptr);

    // fc2 + residual -> out
    gemm_bf16<2><<<dim3(256 / 128, TOKS / 128), 256, BF_SMEM>>>(
        h1, w2bf, fc2b, out, TOKS, 256, 1024, x2);
}